// round 1
// baseline (speedup 1.0000x reference)
#include <cuda_runtime.h>
#include <math.h>

#define SQ     2048
#define HIDDEN 2048
#define NH     32
#define NKV    8
#define HD     64
#define QDIM   (NH * HD)    // 2048
#define KVDIM  (NKV * HD)   // 512

// Scratch buffers (allocation is forbidden; use device globals).
__device__ float g_Q[(size_t)SQ * QDIM];   // 16 MB
__device__ float g_K[(size_t)SQ * KVDIM];  //  4 MB
__device__ float g_V[(size_t)SQ * KVDIM];  //  4 MB
__device__ float g_O[(size_t)SQ * QDIM];   // 16 MB

// ---------------------------------------------------------------------------
// SGEMM: C[M,N] = A[M,K] * B[N,K]^T   (A,B,C row-major; all dims % 128 == 0,
// K % 8 == 0). 128x128 block, 8x8 per thread, BK=8, 256 threads.
// ---------------------------------------------------------------------------
__global__ __launch_bounds__(256) void sgemm_abt(
    const float* __restrict__ A, const float* __restrict__ B,
    float* __restrict__ C, int M, int N, int K)
{
    const int BM = 128, BN = 128, BK = 8, TM = 8, TN = 8;
    __shared__ float As[BK][BM];
    __shared__ float Bs[BK][BN];

    int bm = blockIdx.y * BM;
    int bn = blockIdx.x * BN;
    int tid = threadIdx.x;
    int tx = tid & 15;          // 0..15 -> N direction
    int ty = tid >> 4;          // 0..15 -> M direction
    int lrow = tid >> 1;        // 0..127
    int lcol = (tid & 1) << 2;  // 0 or 4

    float acc[TM][TN];
#pragma unroll
    for (int i = 0; i < TM; i++)
#pragma unroll
        for (int j = 0; j < TN; j++) acc[i][j] = 0.f;

    const float* Aptr = A + (size_t)(bm + lrow) * K + lcol;
    const float* Bptr = B + (size_t)(bn + lrow) * K + lcol;

    for (int k0 = 0; k0 < K; k0 += BK) {
        float4 a4 = *(const float4*)(Aptr + k0);
        float4 b4 = *(const float4*)(Bptr + k0);
        As[lcol + 0][lrow] = a4.x;
        As[lcol + 1][lrow] = a4.y;
        As[lcol + 2][lrow] = a4.z;
        As[lcol + 3][lrow] = a4.w;
        Bs[lcol + 0][lrow] = b4.x;
        Bs[lcol + 1][lrow] = b4.y;
        Bs[lcol + 2][lrow] = b4.z;
        Bs[lcol + 3][lrow] = b4.w;
        __syncthreads();

#pragma unroll
        for (int kk = 0; kk < BK; kk++) {
            float ar[TM], br[TN];
#pragma unroll
            for (int i = 0; i < TM; i++) ar[i] = As[kk][ty * TM + i];
#pragma unroll
            for (int j = 0; j < TN; j++) br[j] = Bs[kk][tx * TN + j];
#pragma unroll
            for (int i = 0; i < TM; i++)
#pragma unroll
                for (int j = 0; j < TN; j++)
                    acc[i][j] = fmaf(ar[i], br[j], acc[i][j]);
        }
        __syncthreads();
    }

#pragma unroll
    for (int i = 0; i < TM; i++) {
        int row = bm + ty * TM + i;
        float* cp = C + (size_t)row * N + bn + tx * TN;
        float4 v0 = make_float4(acc[i][0], acc[i][1], acc[i][2], acc[i][3]);
        float4 v1 = make_float4(acc[i][4], acc[i][5], acc[i][6], acc[i][7]);
        *(float4*)(cp + 0) = v0;
        *(float4*)(cp + 4) = v1;
    }
}

// ---------------------------------------------------------------------------
// RoPE in place on X[S, nheads*HD]. One thread per (s, h, j<HD/2) pair.
// x[j]   <- x[j]*cos - x[j+32]*sin
// x[j+32]<- x[j+32]*cos + x[j]*sin
// ---------------------------------------------------------------------------
__global__ void rope_kernel(float* __restrict__ X, int nheads, int total)
{
    int idx = blockIdx.x * blockDim.x + threadIdx.x;
    if (idx >= total) return;
    int j = idx & (HD / 2 - 1);            // 0..31
    int h = (idx >> 5) % nheads;
    int s = idx / ((HD / 2) * nheads);

    // inv_freq = 10000^(-2j/64) = 2^(-log2(10000)*2j/64)
    float invf = exp2f(-13.2877123795494f * (float)(2 * j) / (float)HD);
    float ang = (float)s * invf;
    float sn, cs;
    sincosf(ang, &sn, &cs);

    float* p = X + (size_t)s * nheads * HD + h * HD + j;
    float x1 = p[0];
    float x2 = p[HD / 2];
    p[0]      = x1 * cs - x2 * sn;
    p[HD / 2] = x2 * cs + x1 * sn;
}

// ---------------------------------------------------------------------------
// Causal flash attention with GQA.
// Grid: (SQ/64, NH). Block: 64 threads, thread = one query row of the tile.
// Q[S, QDIM], K/V[S, KVDIM] (post-RoPE), O[S, QDIM].
// ---------------------------------------------------------------------------
__global__ __launch_bounds__(64) void flash_attn(
    const float* __restrict__ Q, const float* __restrict__ K,
    const float* __restrict__ V, float* __restrict__ O)
{
    __shared__ float Ks[64][HD];  // 16 KB
    __shared__ float Vs[64][HD];  // 16 KB

    int qt  = blockIdx.x;
    int h   = blockIdx.y;
    int kvh = h / (NH / NKV);
    int row = threadIdx.x;        // 0..63
    int qrow = qt * 64 + row;

    // Q row in registers, pre-scaled by 1/sqrt(HD)
    float q[HD];
    {
        const float* qp = Q + (size_t)qrow * QDIM + h * HD;
#pragma unroll
        for (int d4 = 0; d4 < HD / 4; d4++) {
            float4 v = ((const float4*)qp)[d4];
            q[d4 * 4 + 0] = v.x * 0.125f;
            q[d4 * 4 + 1] = v.y * 0.125f;
            q[d4 * 4 + 2] = v.z * 0.125f;
            q[d4 * 4 + 3] = v.w * 0.125f;
        }
    }

    float m = -1e30f, l = 0.f;
    float acc[HD];
#pragma unroll
    for (int d = 0; d < HD; d++) acc[d] = 0.f;

    for (int kt = 0; kt <= qt; kt++) {
        // Stage K/V tile (each thread loads one row)
        const float* kp = K + (size_t)(kt * 64 + row) * KVDIM + kvh * HD;
        const float* vp = V + (size_t)(kt * 64 + row) * KVDIM + kvh * HD;
#pragma unroll
        for (int d4 = 0; d4 < HD / 4; d4++) {
            ((float4*)Ks[row])[d4] = ((const float4*)kp)[d4];
            ((float4*)Vs[row])[d4] = ((const float4*)vp)[d4];
        }
        __syncthreads();

        bool diag = (kt == qt);
#pragma unroll 1
        for (int j0 = 0; j0 < 64; j0 += 16) {
            float sc[16];
            float tmax = m;
#pragma unroll
            for (int jj = 0; jj < 16; jj++) {
                int j = j0 + jj;
                float s = 0.f;
#pragma unroll
                for (int d = 0; d < HD; d++) s = fmaf(q[d], Ks[j][d], s);
                bool valid = !diag || (j <= row);
                s = valid ? s : -1e30f;
                sc[jj] = s;
                tmax = fmaxf(tmax, s);
            }
            float corr = __expf(m - tmax);
            m = tmax;
            l *= corr;
#pragma unroll
            for (int d = 0; d < HD; d++) acc[d] *= corr;
#pragma unroll
            for (int jj = 0; jj < 16; jj++) {
                float p = __expf(sc[jj] - m);
                l += p;
#pragma unroll
                for (int d = 0; d < HD; d++)
                    acc[d] = fmaf(p, Vs[j0 + jj][d], acc[d]);
            }
        }
        __syncthreads();
    }

    float inv = 1.f / l;
    float* op = O + (size_t)qrow * QDIM + h * HD;
#pragma unroll
    for (int d4 = 0; d4 < HD / 4; d4++) {
        float4 v;
        v.x = acc[d4 * 4 + 0] * inv;
        v.y = acc[d4 * 4 + 1] * inv;
        v.z = acc[d4 * 4 + 2] * inv;
        v.w = acc[d4 * 4 + 3] * inv;
        ((float4*)op)[d4] = v;
    }
}

// ---------------------------------------------------------------------------
extern "C" void kernel_launch(void* const* d_in, const int* in_sizes, int n_in,
                              void* d_out, int out_size)
{
    const float* hs = (const float*)d_in[0];
    const float* Wq = (const float*)d_in[1];
    const float* Wk = (const float*)d_in[2];
    const float* Wv = (const float*)d_in[3];
    const float* Wo = (const float*)d_in[4];
    float* out = (float*)d_out;

    float *Qp, *Kp, *Vp, *Op;
    cudaGetSymbolAddress((void**)&Qp, g_Q);
    cudaGetSymbolAddress((void**)&Kp, g_K);
    cudaGetSymbolAddress((void**)&Vp, g_V);
    cudaGetSymbolAddress((void**)&Op, g_O);

    dim3 blk(256);
    // QKV projections
    sgemm_abt<<<dim3(QDIM / 128, SQ / 128), blk>>>(hs, Wq, Qp, SQ, QDIM, HIDDEN);
    sgemm_abt<<<dim3(KVDIM / 128, SQ / 128), blk>>>(hs, Wk, Kp, SQ, KVDIM, HIDDEN);
    sgemm_abt<<<dim3(KVDIM / 128, SQ / 128), blk>>>(hs, Wv, Vp, SQ, KVDIM, HIDDEN);

    // RoPE on Q and K
    {
        int totq = SQ * NH * (HD / 2);
        int totk = SQ * NKV * (HD / 2);
        rope_kernel<<<(totq + 255) / 256, 256>>>(Qp, NH, totq);
        rope_kernel<<<(totk + 255) / 256, 256>>>(Kp, NKV, totk);
    }

    // Causal flash attention with GQA
    flash_attn<<<dim3(SQ / 64, NH), 64>>>(Qp, Kp, Vp, Op);

    // Output projection
    sgemm_abt<<<dim3(HIDDEN / 128, SQ / 128), blk>>>(Op, Wo, out, SQ, HIDDEN, QDIM);
}

// round 2
// speedup vs baseline: 1.6747x; 1.6747x over previous
#include <cuda_runtime.h>
#include <math.h>
#include <stdint.h>

#define SQ     2048
#define HIDDEN 2048
#define NH     32
#define NKV    8
#define HD     64
#define QDIM   (NH * HD)    // 2048
#define KVDIM  (NKV * HD)   // 512

// Scratch buffers (allocation is forbidden; use device globals).
__device__ float g_Q[(size_t)SQ * QDIM];   // 16 MB
__device__ float g_K[(size_t)SQ * KVDIM];  //  4 MB
__device__ float g_V[(size_t)SQ * KVDIM];  //  4 MB
__device__ float g_O[(size_t)SQ * QDIM];   // 16 MB

// ---------------------------------------------------------------------------
// TF32 tensor-core GEMM: C[M,N] = A[M,K] * B[N,K]^T  (row-major, K contig in
// both A and B). Block tile 128x128, BK=16, 256 threads = 8 warps, warp tile
// 64x32 (4x4 mma.m16n8k8 tiles). 2-stage smem double buffer; inputs converted
// to tf32 (round-to-nearest) at SMEM store time.
// ---------------------------------------------------------------------------
#define BM 128
#define BN 128
#define BK 16
#define SSTR 20   // smem row stride (floats): 20 % 32 == 4 -> conflict-free frags

__device__ __forceinline__ uint32_t f2tf32(float x) {
    uint32_t u;
    asm("cvt.rna.tf32.f32 %0, %1;" : "=r"(u) : "f"(x));
    return u;
}

__device__ __forceinline__ void mma_tf32(float* d, const uint32_t* a, const uint32_t* b) {
    asm volatile(
        "mma.sync.aligned.m16n8k8.row.col.f32.tf32.tf32.f32 "
        "{%0,%1,%2,%3}, {%4,%5,%6,%7}, {%8,%9}, {%0,%1,%2,%3};\n"
        : "+f"(d[0]), "+f"(d[1]), "+f"(d[2]), "+f"(d[3])
        : "r"(a[0]), "r"(a[1]), "r"(a[2]), "r"(a[3]), "r"(b[0]), "r"(b[1]));
}

__global__ __launch_bounds__(256) void gemm_tf32_abt(
    const float* __restrict__ A, const float* __restrict__ B,
    float* __restrict__ C, int M, int N, int K)
{
    __shared__ uint32_t As[2][BM][SSTR];
    __shared__ uint32_t Bs[2][BM][SSTR];

    const int bm = blockIdx.y * BM;
    const int bn = blockIdx.x * BN;
    const int tid = threadIdx.x;
    const int wid = tid >> 5;
    const int lane = tid & 31;
    const int g = lane >> 2;     // groupID
    const int ctg = lane & 3;    // thread-in-group
    const int wm = wid & 1;      // 2 warp rows  (M)
    const int wn = wid >> 1;     // 4 warp cols  (N)

    // gmem load mapping: 512 float4 slots per tile, 2 per thread
    const int i0 = tid;          // slot 0
    const int i1 = tid + 256;    // slot 1
    const int r0 = i0 >> 2, c0 = i0 & 3;
    const int r1 = i1 >> 2, c1 = i1 & 3;

    const int niter = K / BK;

    float4 abuf0, abuf1, bbuf0, bbuf1;

    auto ldg_tile = [&](int it) {
        int k0 = it * BK;
        abuf0 = *(const float4*)(A + (size_t)(bm + r0) * K + k0 + c0 * 4);
        abuf1 = *(const float4*)(A + (size_t)(bm + r1) * K + k0 + c1 * 4);
        bbuf0 = *(const float4*)(B + (size_t)(bn + r0) * K + k0 + c0 * 4);
        bbuf1 = *(const float4*)(B + (size_t)(bn + r1) * K + k0 + c1 * 4);
    };
    auto sts_tile = [&](int st) {
        uint32_t* pa0 = &As[st][r0][c0 * 4];
        pa0[0] = f2tf32(abuf0.x); pa0[1] = f2tf32(abuf0.y);
        pa0[2] = f2tf32(abuf0.z); pa0[3] = f2tf32(abuf0.w);
        uint32_t* pa1 = &As[st][r1][c1 * 4];
        pa1[0] = f2tf32(abuf1.x); pa1[1] = f2tf32(abuf1.y);
        pa1[2] = f2tf32(abuf1.z); pa1[3] = f2tf32(abuf1.w);
        uint32_t* pb0 = &Bs[st][r0][c0 * 4];
        pb0[0] = f2tf32(bbuf0.x); pb0[1] = f2tf32(bbuf0.y);
        pb0[2] = f2tf32(bbuf0.z); pb0[3] = f2tf32(bbuf0.w);
        uint32_t* pb1 = &Bs[st][r1][c1 * 4];
        pb1[0] = f2tf32(bbuf1.x); pb1[1] = f2tf32(bbuf1.y);
        pb1[2] = f2tf32(bbuf1.z); pb1[3] = f2tf32(bbuf1.w);
    };

    float acc[4][4][4];
#pragma unroll
    for (int mt = 0; mt < 4; mt++)
#pragma unroll
        for (int nt = 0; nt < 4; nt++)
#pragma unroll
            for (int i = 0; i < 4; i++) acc[mt][nt][i] = 0.f;

    // prologue: tile0 -> smem stage0; tile1 -> regs
    ldg_tile(0);
    sts_tile(0);
    if (niter > 1) ldg_tile(1);
    __syncthreads();

    for (int it = 0; it < niter; it++) {
        int st = it & 1;
        // stage next tile (loaded last iteration) into the other buffer
        if (it + 1 < niter) sts_tile((it + 1) & 1);
        // prefetch tile it+2
        if (it + 2 < niter) ldg_tile(it + 2);

        // compute on stage st
#pragma unroll
        for (int kk = 0; kk < BK; kk += 8) {
            uint32_t af[4][4], bf[4][2];
#pragma unroll
            for (int mt = 0; mt < 4; mt++) {
                int m0 = wm * 64 + mt * 16 + g;
                af[mt][0] = As[st][m0][kk + ctg];
                af[mt][1] = As[st][m0 + 8][kk + ctg];
                af[mt][2] = As[st][m0][kk + ctg + 4];
                af[mt][3] = As[st][m0 + 8][kk + ctg + 4];
            }
#pragma unroll
            for (int nt = 0; nt < 4; nt++) {
                int n0 = wn * 32 + nt * 8 + g;
                bf[nt][0] = Bs[st][n0][kk + ctg];
                bf[nt][1] = Bs[st][n0][kk + ctg + 4];
            }
#pragma unroll
            for (int mt = 0; mt < 4; mt++)
#pragma unroll
                for (int nt = 0; nt < 4; nt++)
                    mma_tf32(acc[mt][nt], af[mt], bf[nt]);
        }
        __syncthreads();
    }

    // epilogue: c0,c1 -> (row g, col 2ctg..2ctg+1); c2,c3 -> row g+8
#pragma unroll
    for (int mt = 0; mt < 4; mt++) {
        int mrow = bm + wm * 64 + mt * 16 + g;
#pragma unroll
        for (int nt = 0; nt < 4; nt++) {
            int ncol = bn + wn * 32 + nt * 8 + 2 * ctg;
            float2 v0 = make_float2(acc[mt][nt][0], acc[mt][nt][1]);
            float2 v1 = make_float2(acc[mt][nt][2], acc[mt][nt][3]);
            *(float2*)(C + (size_t)mrow * N + ncol) = v0;
            *(float2*)(C + (size_t)(mrow + 8) * N + ncol) = v1;
        }
    }
}

// ---------------------------------------------------------------------------
// RoPE in place on X[S, nheads*HD]. One thread per (s, h, j<HD/2) pair.
// ---------------------------------------------------------------------------
__global__ void rope_kernel(float* __restrict__ X, int nheads, int total)
{
    int idx = blockIdx.x * blockDim.x + threadIdx.x;
    if (idx >= total) return;
    int j = idx & (HD / 2 - 1);            // 0..31
    int h = (idx >> 5) % nheads;
    int s = idx / ((HD / 2) * nheads);

    float invf = exp2f(-13.2877123795494f * (float)(2 * j) / (float)HD);
    float ang = (float)s * invf;
    float sn, cs;
    sincosf(ang, &sn, &cs);

    float* p = X + (size_t)s * nheads * HD + h * HD + j;
    float x1 = p[0];
    float x2 = p[HD / 2];
    p[0]      = x1 * cs - x2 * sn;
    p[HD / 2] = x2 * cs + x1 * sn;
}

// ---------------------------------------------------------------------------
// Causal flash attention with GQA (fp32).
// Grid: (SQ/64, NH). Block: 64 threads, thread = one query row of the tile.
// ---------------------------------------------------------------------------
__global__ __launch_bounds__(64) void flash_attn(
    const float* __restrict__ Q, const float* __restrict__ K,
    const float* __restrict__ V, float* __restrict__ O)
{
    __shared__ float Ks[64][HD];
    __shared__ float Vs[64][HD];

    int qt  = blockIdx.x;
    int h   = blockIdx.y;
    int kvh = h / (NH / NKV);
    int row = threadIdx.x;
    int qrow = qt * 64 + row;

    float q[HD];
    {
        const float* qp = Q + (size_t)qrow * QDIM + h * HD;
#pragma unroll
        for (int d4 = 0; d4 < HD / 4; d4++) {
            float4 v = ((const float4*)qp)[d4];
            q[d4 * 4 + 0] = v.x * 0.125f;
            q[d4 * 4 + 1] = v.y * 0.125f;
            q[d4 * 4 + 2] = v.z * 0.125f;
            q[d4 * 4 + 3] = v.w * 0.125f;
        }
    }

    float m = -1e30f, l = 0.f;
    float acc[HD];
#pragma unroll
    for (int d = 0; d < HD; d++) acc[d] = 0.f;

    for (int kt = 0; kt <= qt; kt++) {
        const float* kp = K + (size_t)(kt * 64 + row) * KVDIM + kvh * HD;
        const float* vp = V + (size_t)(kt * 64 + row) * KVDIM + kvh * HD;
#pragma unroll
        for (int d4 = 0; d4 < HD / 4; d4++) {
            ((float4*)Ks[row])[d4] = ((const float4*)kp)[d4];
            ((float4*)Vs[row])[d4] = ((const float4*)vp)[d4];
        }
        __syncthreads();

        bool diag = (kt == qt);
#pragma unroll 1
        for (int j0 = 0; j0 < 64; j0 += 16) {
            float sc[16];
            float tmax = m;
#pragma unroll
            for (int jj = 0; jj < 16; jj++) {
                int j = j0 + jj;
                float s = 0.f;
#pragma unroll
                for (int d = 0; d < HD; d++) s = fmaf(q[d], Ks[j][d], s);
                bool valid = !diag || (j <= row);
                s = valid ? s : -1e30f;
                sc[jj] = s;
                tmax = fmaxf(tmax, s);
            }
            float corr = __expf(m - tmax);
            m = tmax;
            l *= corr;
#pragma unroll
            for (int d = 0; d < HD; d++) acc[d] *= corr;
#pragma unroll
            for (int jj = 0; jj < 16; jj++) {
                float p = __expf(sc[jj] - m);
                l += p;
#pragma unroll
                for (int d = 0; d < HD; d++)
                    acc[d] = fmaf(p, Vs[j0 + jj][d], acc[d]);
            }
        }
        __syncthreads();
    }

    float inv = 1.f / l;
    float* op = O + (size_t)qrow * QDIM + h * HD;
#pragma unroll
    for (int d4 = 0; d4 < HD / 4; d4++) {
        float4 v;
        v.x = acc[d4 * 4 + 0] * inv;
        v.y = acc[d4 * 4 + 1] * inv;
        v.z = acc[d4 * 4 + 2] * inv;
        v.w = acc[d4 * 4 + 3] * inv;
        ((float4*)op)[d4] = v;
    }
}

// ---------------------------------------------------------------------------
extern "C" void kernel_launch(void* const* d_in, const int* in_sizes, int n_in,
                              void* d_out, int out_size)
{
    const float* hs = (const float*)d_in[0];
    const float* Wq = (const float*)d_in[1];
    const float* Wk = (const float*)d_in[2];
    const float* Wv = (const float*)d_in[3];
    const float* Wo = (const float*)d_in[4];
    float* out = (float*)d_out;

    float *Qp, *Kp, *Vp, *Op;
    cudaGetSymbolAddress((void**)&Qp, g_Q);
    cudaGetSymbolAddress((void**)&Kp, g_K);
    cudaGetSymbolAddress((void**)&Vp, g_V);
    cudaGetSymbolAddress((void**)&Op, g_O);

    dim3 blk(256);
    // QKV projections (tf32 tensor cores)
    gemm_tf32_abt<<<dim3(QDIM / BN, SQ / BM), blk>>>(hs, Wq, Qp, SQ, QDIM, HIDDEN);
    gemm_tf32_abt<<<dim3(KVDIM / BN, SQ / BM), blk>>>(hs, Wk, Kp, SQ, KVDIM, HIDDEN);
    gemm_tf32_abt<<<dim3(KVDIM / BN, SQ / BM), blk>>>(hs, Wv, Vp, SQ, KVDIM, HIDDEN);

    // RoPE on Q and K
    {
        int totq = SQ * NH * (HD / 2);
        int totk = SQ * NKV * (HD / 2);
        rope_kernel<<<(totq + 255) / 256, 256>>>(Qp, NH, totq);
        rope_kernel<<<(totk + 255) / 256, 256>>>(Kp, NKV, totk);
    }

    // Causal flash attention with GQA
    flash_attn<<<dim3(SQ / 64, NH), 64>>>(Qp, Kp, Vp, Op);

    // Output projection (tf32 tensor cores)
    gemm_tf32_abt<<<dim3(HIDDEN / BN, SQ / BM), blk>>>(Op, Wo, out, SQ, HIDDEN, QDIM);
}

// round 3
// speedup vs baseline: 3.9597x; 2.3645x over previous
#include <cuda_runtime.h>
#include <math.h>
#include <stdint.h>

#define SQ     2048
#define HIDDEN 2048
#define NH     32
#define NKV    8
#define HD     64
#define QDIM   (NH * HD)    // 2048
#define KVDIM  (NKV * HD)   // 512

// Scratch buffers (allocation is forbidden; use device globals).
__device__ float g_Q[(size_t)SQ * QDIM];   // 16 MB
__device__ float g_K[(size_t)SQ * KVDIM];  //  4 MB
__device__ float g_V[(size_t)SQ * KVDIM];  //  4 MB
__device__ float g_O[(size_t)SQ * QDIM];   // 16 MB

__device__ __forceinline__ uint32_t f2tf32(float x) {
    uint32_t u;
    asm("cvt.rna.tf32.f32 %0, %1;" : "=r"(u) : "f"(x));
    return u;
}

__device__ __forceinline__ void mma_tf32(float* d, const uint32_t* a, const uint32_t* b) {
    asm volatile(
        "mma.sync.aligned.m16n8k8.row.col.f32.tf32.tf32.f32 "
        "{%0,%1,%2,%3}, {%4,%5,%6,%7}, {%8,%9}, {%0,%1,%2,%3};\n"
        : "+f"(d[0]), "+f"(d[1]), "+f"(d[2]), "+f"(d[3])
        : "r"(a[0]), "r"(a[1]), "r"(a[2]), "r"(a[3]), "r"(b[0]), "r"(b[1]));
}

// ---------------------------------------------------------------------------
// TF32 tensor-core GEMM: C[M,N] = A[M,K] * B[N,K]^T. 128x128 block, BK=16,
// 256 threads = 8 warps, warp tile 64x32. 2-stage smem double buffer.
// ---------------------------------------------------------------------------
#define BM 128
#define BN 128
#define BK 16
#define SSTR 20

__global__ __launch_bounds__(256) void gemm_tf32_abt(
    const float* __restrict__ A, const float* __restrict__ B,
    float* __restrict__ C, int M, int N, int K)
{
    __shared__ uint32_t As[2][BM][SSTR];
    __shared__ uint32_t Bs[2][BM][SSTR];

    const int bm = blockIdx.y * BM;
    const int bn = blockIdx.x * BN;
    const int tid = threadIdx.x;
    const int wid = tid >> 5;
    const int lane = tid & 31;
    const int g = lane >> 2;
    const int ctg = lane & 3;
    const int wm = wid & 1;
    const int wn = wid >> 1;

    const int i0 = tid;
    const int i1 = tid + 256;
    const int r0 = i0 >> 2, c0 = i0 & 3;
    const int r1 = i1 >> 2, c1 = i1 & 3;

    const int niter = K / BK;

    float4 abuf0, abuf1, bbuf0, bbuf1;

    auto ldg_tile = [&](int it) {
        int k0 = it * BK;
        abuf0 = *(const float4*)(A + (size_t)(bm + r0) * K + k0 + c0 * 4);
        abuf1 = *(const float4*)(A + (size_t)(bm + r1) * K + k0 + c1 * 4);
        bbuf0 = *(const float4*)(B + (size_t)(bn + r0) * K + k0 + c0 * 4);
        bbuf1 = *(const float4*)(B + (size_t)(bn + r1) * K + k0 + c1 * 4);
    };
    auto sts_tile = [&](int st) {
        uint32_t* pa0 = &As[st][r0][c0 * 4];
        pa0[0] = f2tf32(abuf0.x); pa0[1] = f2tf32(abuf0.y);
        pa0[2] = f2tf32(abuf0.z); pa0[3] = f2tf32(abuf0.w);
        uint32_t* pa1 = &As[st][r1][c1 * 4];
        pa1[0] = f2tf32(abuf1.x); pa1[1] = f2tf32(abuf1.y);
        pa1[2] = f2tf32(abuf1.z); pa1[3] = f2tf32(abuf1.w);
        uint32_t* pb0 = &Bs[st][r0][c0 * 4];
        pb0[0] = f2tf32(bbuf0.x); pb0[1] = f2tf32(bbuf0.y);
        pb0[2] = f2tf32(bbuf0.z); pb0[3] = f2tf32(bbuf0.w);
        uint32_t* pb1 = &Bs[st][r1][c1 * 4];
        pb1[0] = f2tf32(bbuf1.x); pb1[1] = f2tf32(bbuf1.y);
        pb1[2] = f2tf32(bbuf1.z); pb1[3] = f2tf32(bbuf1.w);
    };

    float acc[4][4][4];
#pragma unroll
    for (int mt = 0; mt < 4; mt++)
#pragma unroll
        for (int nt = 0; nt < 4; nt++)
#pragma unroll
            for (int i = 0; i < 4; i++) acc[mt][nt][i] = 0.f;

    ldg_tile(0);
    sts_tile(0);
    if (niter > 1) ldg_tile(1);
    __syncthreads();

    for (int it = 0; it < niter; it++) {
        int st = it & 1;
        if (it + 1 < niter) sts_tile((it + 1) & 1);
        if (it + 2 < niter) ldg_tile(it + 2);

#pragma unroll
        for (int kk = 0; kk < BK; kk += 8) {
            uint32_t af[4][4], bf[4][2];
#pragma unroll
            for (int mt = 0; mt < 4; mt++) {
                int m0 = wm * 64 + mt * 16 + g;
                af[mt][0] = As[st][m0][kk + ctg];
                af[mt][1] = As[st][m0 + 8][kk + ctg];
                af[mt][2] = As[st][m0][kk + ctg + 4];
                af[mt][3] = As[st][m0 + 8][kk + ctg + 4];
            }
#pragma unroll
            for (int nt = 0; nt < 4; nt++) {
                int n0 = wn * 32 + nt * 8 + g;
                bf[nt][0] = Bs[st][n0][kk + ctg];
                bf[nt][1] = Bs[st][n0][kk + ctg + 4];
            }
#pragma unroll
            for (int mt = 0; mt < 4; mt++)
#pragma unroll
                for (int nt = 0; nt < 4; nt++)
                    mma_tf32(acc[mt][nt], af[mt], bf[nt]);
        }
        __syncthreads();
    }

#pragma unroll
    for (int mt = 0; mt < 4; mt++) {
        int mrow = bm + wm * 64 + mt * 16 + g;
#pragma unroll
        for (int nt = 0; nt < 4; nt++) {
            int ncol = bn + wn * 32 + nt * 8 + 2 * ctg;
            float2 v0 = make_float2(acc[mt][nt][0], acc[mt][nt][1]);
            float2 v1 = make_float2(acc[mt][nt][2], acc[mt][nt][3]);
            *(float2*)(C + (size_t)mrow * N + ncol) = v0;
            *(float2*)(C + (size_t)(mrow + 8) * N + ncol) = v1;
        }
    }
}

// ---------------------------------------------------------------------------
// RoPE in place on X[S, nheads*HD].
// ---------------------------------------------------------------------------
__global__ void rope_kernel(float* __restrict__ X, int nheads, int total)
{
    int idx = blockIdx.x * blockDim.x + threadIdx.x;
    if (idx >= total) return;
    int j = idx & (HD / 2 - 1);
    int h = (idx >> 5) % nheads;
    int s = idx / ((HD / 2) * nheads);

    float invf = exp2f(-13.2877123795494f * (float)(2 * j) / (float)HD);
    float ang = (float)s * invf;
    float sn, cs;
    sincosf(ang, &sn, &cs);

    float* p = X + (size_t)s * nheads * HD + h * HD + j;
    float x1 = p[0];
    float x2 = p[HD / 2];
    p[0]      = x1 * cs - x2 * sn;
    p[HD / 2] = x2 * cs + x1 * sn;
}

// ---------------------------------------------------------------------------
// Tensor-core causal flash attention with GQA (tf32 mma).
// Grid: (SQ/128, NH). Block: 256 threads = 8 warps; warp w owns q rows
// [w*16, w*16+16) of the 128-row tile. KV tiles of 64.
// ---------------------------------------------------------------------------
#define KSTR 68   // 68 % 32 == 4 -> conflict-free (row=base+g, col=ctg) reads
#define VSTR 72   // 72 % 32 == 8 -> conflict-free (row=j0+ctg, col=d0+g) reads
#define PSTR 68

#define ATT_SMEM_U32 (64 * KSTR + 64 * VSTR + 128 * PSTR)

__global__ __launch_bounds__(256) void flash_attn_tc(
    const float* __restrict__ Q, const float* __restrict__ K,
    const float* __restrict__ V, float* __restrict__ O)
{
    extern __shared__ uint32_t sm[];
    uint32_t* Ks  = sm;                       // [64][KSTR]
    uint32_t* Vs  = sm + 64 * KSTR;           // [64][VSTR]
    uint32_t* QPs = sm + 64 * KSTR + 64 * VSTR; // [128][PSTR], Q then P

    const int qt  = blockIdx.x;
    const int h   = blockIdx.y;
    const int kvh = h >> 2;                   // NH/NKV = 4
    const int tid = threadIdx.x;
    const int wid = tid >> 5;
    const int lane = tid & 31;
    const int g = lane >> 2;
    const int ctg = lane & 3;
    const int lrow0 = wid * 16 + g;           // local q row for c0/c1
    // global q rows for this thread
    const int grow0 = qt * 128 + lrow0;
    const int grow1 = grow0 + 8;

    // ---- stage Q tile (scaled by 1/8) into QPs, pick up register fragments
    for (int i = tid; i < 128 * 16; i += 256) {
        int r = i >> 4, c4 = i & 15;
        float4 v = *(const float4*)(Q + (size_t)(qt * 128 + r) * QDIM + h * HD + c4 * 4);
        uint32_t* p = QPs + r * PSTR + c4 * 4;
        p[0] = f2tf32(v.x * 0.125f);
        p[1] = f2tf32(v.y * 0.125f);
        p[2] = f2tf32(v.z * 0.125f);
        p[3] = f2tf32(v.w * 0.125f);
    }
    __syncthreads();

    uint32_t qf[8][4];
#pragma unroll
    for (int a = 0; a < 8; a++) {
        qf[a][0] = QPs[lrow0 * PSTR + a * 8 + ctg];
        qf[a][1] = QPs[(lrow0 + 8) * PSTR + a * 8 + ctg];
        qf[a][2] = QPs[lrow0 * PSTR + a * 8 + ctg + 4];
        qf[a][3] = QPs[(lrow0 + 8) * PSTR + a * 8 + ctg + 4];
    }
    __syncthreads();   // QPs now free for P

    float acc[8][4];
#pragma unroll
    for (int nt = 0; nt < 8; nt++)
#pragma unroll
        for (int i = 0; i < 4; i++) acc[nt][i] = 0.f;
    float m0 = -1e30f, m1 = -1e30f, l0 = 0.f, l1 = 0.f;

    const int ntiles = 2 * qt + 2;
    for (int kt = 0; kt < ntiles; kt++) {
        // ---- fill K/V tile (tf32 in smem)
        for (int i = tid; i < 64 * 16; i += 256) {
            int r = i >> 4, c4 = i & 15;
            size_t goff = (size_t)(kt * 64 + r) * KVDIM + kvh * HD + c4 * 4;
            float4 kv = *(const float4*)(K + goff);
            uint32_t* pk = Ks + r * KSTR + c4 * 4;
            pk[0] = f2tf32(kv.x); pk[1] = f2tf32(kv.y);
            pk[2] = f2tf32(kv.z); pk[3] = f2tf32(kv.w);
            float4 vv = *(const float4*)(V + goff);
            uint32_t* pv = Vs + r * VSTR + c4 * 4;
            pv[0] = f2tf32(vv.x); pv[1] = f2tf32(vv.y);
            pv[2] = f2tf32(vv.z); pv[3] = f2tf32(vv.w);
        }
        __syncthreads();

        // ---- S = Q K^T  (16 x 64 per warp)
        float sc[8][4];
#pragma unroll
        for (int nt = 0; nt < 8; nt++)
#pragma unroll
            for (int i = 0; i < 4; i++) sc[nt][i] = 0.f;

#pragma unroll
        for (int kk = 0; kk < 8; kk++) {
#pragma unroll
            for (int nt = 0; nt < 8; nt++) {
                uint32_t b[2];
                b[0] = Ks[(nt * 8 + g) * KSTR + kk * 8 + ctg];
                b[1] = Ks[(nt * 8 + g) * KSTR + kk * 8 + ctg + 4];
                mma_tf32(sc[nt], qf[kk], b);
            }
        }

        // ---- causal mask (only needed on the two diagonal tiles)
        if (kt >= 2 * qt) {
#pragma unroll
            for (int nt = 0; nt < 8; nt++) {
                int col = kt * 64 + nt * 8 + 2 * ctg;
                if (col > grow0)     sc[nt][0] = -1e30f;
                if (col + 1 > grow0) sc[nt][1] = -1e30f;
                if (col > grow1)     sc[nt][2] = -1e30f;
                if (col + 1 > grow1) sc[nt][3] = -1e30f;
            }
        }

        // ---- online softmax (rows grow0, grow1)
        float tmax0 = -1e30f, tmax1 = -1e30f;
#pragma unroll
        for (int nt = 0; nt < 8; nt++) {
            tmax0 = fmaxf(tmax0, fmaxf(sc[nt][0], sc[nt][1]));
            tmax1 = fmaxf(tmax1, fmaxf(sc[nt][2], sc[nt][3]));
        }
#pragma unroll
        for (int off = 1; off <= 2; off <<= 1) {
            tmax0 = fmaxf(tmax0, __shfl_xor_sync(0xffffffffu, tmax0, off));
            tmax1 = fmaxf(tmax1, __shfl_xor_sync(0xffffffffu, tmax1, off));
        }
        float m0n = fmaxf(m0, tmax0);
        float m1n = fmaxf(m1, tmax1);
        float corr0 = __expf(m0 - m0n);
        float corr1 = __expf(m1 - m1n);
        m0 = m0n; m1 = m1n;

        float sum0 = 0.f, sum1 = 0.f;
#pragma unroll
        for (int nt = 0; nt < 8; nt++) {
            float p0 = __expf(sc[nt][0] - m0);
            float p1 = __expf(sc[nt][1] - m0);
            float p2 = __expf(sc[nt][2] - m1);
            float p3 = __expf(sc[nt][3] - m1);
            sum0 += p0 + p1;
            sum1 += p2 + p3;
            sc[nt][0] = p0; sc[nt][1] = p1; sc[nt][2] = p2; sc[nt][3] = p3;
        }
#pragma unroll
        for (int off = 1; off <= 2; off <<= 1) {
            sum0 += __shfl_xor_sync(0xffffffffu, sum0, off);
            sum1 += __shfl_xor_sync(0xffffffffu, sum1, off);
        }
        l0 = l0 * corr0 + sum0;
        l1 = l1 * corr1 + sum1;
#pragma unroll
        for (int nt = 0; nt < 8; nt++) {
            acc[nt][0] *= corr0; acc[nt][1] *= corr0;
            acc[nt][2] *= corr1; acc[nt][3] *= corr1;
        }

        // ---- P -> smem (tf32), per-warp region
#pragma unroll
        for (int nt = 0; nt < 8; nt++) {
            uint32_t* p0 = QPs + lrow0 * PSTR + nt * 8 + 2 * ctg;
            p0[0] = f2tf32(sc[nt][0]);
            p0[1] = f2tf32(sc[nt][1]);
            uint32_t* p1 = QPs + (lrow0 + 8) * PSTR + nt * 8 + 2 * ctg;
            p1[0] = f2tf32(sc[nt][2]);
            p1[1] = f2tf32(sc[nt][3]);
        }
        __syncwarp();

        // ---- O += P V  (16 x 64 per warp)
#pragma unroll
        for (int j8 = 0; j8 < 8; j8++) {
            uint32_t a[4];
            a[0] = QPs[lrow0 * PSTR + j8 * 8 + ctg];
            a[1] = QPs[(lrow0 + 8) * PSTR + j8 * 8 + ctg];
            a[2] = QPs[lrow0 * PSTR + j8 * 8 + ctg + 4];
            a[3] = QPs[(lrow0 + 8) * PSTR + j8 * 8 + ctg + 4];
#pragma unroll
            for (int nt = 0; nt < 8; nt++) {
                uint32_t b[2];
                b[0] = Vs[(j8 * 8 + ctg) * VSTR + nt * 8 + g];
                b[1] = Vs[(j8 * 8 + ctg + 4) * VSTR + nt * 8 + g];
                mma_tf32(acc[nt], a, b);
            }
        }
        __syncwarp();
        __syncthreads();   // before next tile overwrites Ks/Vs
    }

    // ---- epilogue
    float inv0 = 1.f / l0;
    float inv1 = 1.f / l1;
#pragma unroll
    for (int nt = 0; nt < 8; nt++) {
        int col = h * HD + nt * 8 + 2 * ctg;
        float2 v0 = make_float2(acc[nt][0] * inv0, acc[nt][1] * inv0);
        float2 v1 = make_float2(acc[nt][2] * inv1, acc[nt][3] * inv1);
        *(float2*)(O + (size_t)grow0 * QDIM + col) = v0;
        *(float2*)(O + (size_t)grow1 * QDIM + col) = v1;
    }
}

// ---------------------------------------------------------------------------
extern "C" void kernel_launch(void* const* d_in, const int* in_sizes, int n_in,
                              void* d_out, int out_size)
{
    const float* hs = (const float*)d_in[0];
    const float* Wq = (const float*)d_in[1];
    const float* Wk = (const float*)d_in[2];
    const float* Wv = (const float*)d_in[3];
    const float* Wo = (const float*)d_in[4];
    float* out = (float*)d_out;

    float *Qp, *Kp, *Vp, *Op;
    cudaGetSymbolAddress((void**)&Qp, g_Q);
    cudaGetSymbolAddress((void**)&Kp, g_K);
    cudaGetSymbolAddress((void**)&Vp, g_V);
    cudaGetSymbolAddress((void**)&Op, g_O);

    static bool attr_done = false;
    if (!attr_done) {
        cudaFuncSetAttribute(flash_attn_tc,
                             cudaFuncAttributeMaxDynamicSharedMemorySize,
                             ATT_SMEM_U32 * 4);
        attr_done = true;
    }

    dim3 blk(256);
    gemm_tf32_abt<<<dim3(QDIM / BN, SQ / BM), blk>>>(hs, Wq, Qp, SQ, QDIM, HIDDEN);
    gemm_tf32_abt<<<dim3(KVDIM / BN, SQ / BM), blk>>>(hs, Wk, Kp, SQ, KVDIM, HIDDEN);
    gemm_tf32_abt<<<dim3(KVDIM / BN, SQ / BM), blk>>>(hs, Wv, Vp, SQ, KVDIM, HIDDEN);

    {
        int totq = SQ * NH * (HD / 2);
        int totk = SQ * NKV * (HD / 2);
        rope_kernel<<<(totq + 255) / 256, 256>>>(Qp, NH, totq);
        rope_kernel<<<(totk + 255) / 256, 256>>>(Kp, NKV, totk);
    }

    flash_attn_tc<<<dim3(SQ / 128, NH), 256, ATT_SMEM_U32 * 4>>>(Qp, Kp, Vp, Op);

    gemm_tf32_abt<<<dim3(HIDDEN / BN, SQ / BM), blk>>>(Op, Wo, out, SQ, HIDDEN, QDIM);
}

// round 4
// speedup vs baseline: 4.5231x; 1.1423x over previous
#include <cuda_runtime.h>
#include <math.h>
#include <stdint.h>

#define SQ     2048
#define HIDDEN 2048
#define NH     32
#define NKV    8
#define HD     64
#define QDIM   (NH * HD)    // 2048
#define KVDIM  (NKV * HD)   // 512

// Scratch buffers (allocation is forbidden; use device globals).
__device__ float    g_Q[(size_t)SQ * QDIM];
__device__ float    g_K[(size_t)SQ * KVDIM];
__device__ float    g_V[(size_t)SQ * KVDIM];
__device__ float    g_O[(size_t)SQ * QDIM];      // holds tf32-rounded bits
__device__ uint32_t g_hsT[(size_t)SQ * HIDDEN];
__device__ uint32_t g_WqT[(size_t)QDIM * HIDDEN];
__device__ uint32_t g_WkT[(size_t)KVDIM * HIDDEN];
__device__ uint32_t g_WvT[(size_t)KVDIM * HIDDEN];
__device__ uint32_t g_WoT[(size_t)HIDDEN * QDIM];

__device__ __forceinline__ uint32_t f2tf32(float x) {
    uint32_t u;
    asm("cvt.rna.tf32.f32 %0, %1;" : "=r"(u) : "f"(x));
    return u;
}

__device__ __forceinline__ void mma_tf32(float* d, const uint32_t* a, const uint32_t* b) {
    asm volatile(
        "mma.sync.aligned.m16n8k8.row.col.f32.tf32.tf32.f32 "
        "{%0,%1,%2,%3}, {%4,%5,%6,%7}, {%8,%9}, {%0,%1,%2,%3};\n"
        : "+f"(d[0]), "+f"(d[1]), "+f"(d[2]), "+f"(d[3])
        : "r"(a[0]), "r"(a[1]), "r"(a[2]), "r"(a[3]), "r"(b[0]), "r"(b[1]));
}

// ---------------------------------------------------------------------------
// fp32 -> tf32(RNA) elementwise conversion
// ---------------------------------------------------------------------------
__global__ void conv_tf32(const float* __restrict__ in, uint32_t* __restrict__ out, int n)
{
    int i = (blockIdx.x * blockDim.x + threadIdx.x) * 4;
    if (i >= n) return;
    float4 v = *(const float4*)(in + i);
    uint4 o;
    o.x = f2tf32(v.x); o.y = f2tf32(v.y);
    o.z = f2tf32(v.z); o.w = f2tf32(v.w);
    *(uint4*)(out + i) = o;
}

// ---------------------------------------------------------------------------
// cp.async multi-stage tf32 GEMM body: C[M,N] = A[M,K] * B[N,K]^T, inputs
// already tf32. 128x128 block, BK=16, 4 stages, 256 threads = 8 warps,
// warp tile 64x32.
// ---------------------------------------------------------------------------
#define BM 128
#define BN 128
#define BK 16
#define SSTR 20
#define STAGES 4
#define TILE_U32 (BM * SSTR)                       // 2560
#define GEMM_SMEM_BYTES (2 * STAGES * TILE_U32 * 4)  // 80 KB

__device__ __forceinline__ void cp16(uint32_t saddr, const void* g) {
    asm volatile("cp.async.cg.shared.global [%0], [%1], 16;\n" :: "r"(saddr), "l"(g));
}

__device__ __forceinline__ void gemm_body(
    const uint32_t* __restrict__ A, const uint32_t* __restrict__ B,
    float* __restrict__ C, int N, int K, int bm, int bn, uint32_t* sm)
{
    const int tid = threadIdx.x;
    const int wid = tid >> 5, lane = tid & 31;
    const int g = lane >> 2, ctg = lane & 3;
    const int wm = wid & 1, wn = wid >> 1;
    const int r0 = tid >> 2, c0 = tid & 3;
    const int niter = K / BK;

    const uint32_t sbase = (uint32_t)__cvta_generic_to_shared(sm);

    auto issue = [&](int it) {
        if (it < niter) {
            int st = it & (STAGES - 1);
            int k0 = it * BK;
            uint32_t sa = sbase + (uint32_t)(st * TILE_U32 + r0 * SSTR + c0 * 4) * 4u;
            cp16(sa, A + (size_t)(bm + r0) * K + k0 + c0 * 4);
            cp16(sa + 64u * SSTR * 4u, A + (size_t)(bm + r0 + 64) * K + k0 + c0 * 4);
            uint32_t sb = sa + (uint32_t)(STAGES * TILE_U32) * 4u;
            cp16(sb, B + (size_t)(bn + r0) * K + k0 + c0 * 4);
            cp16(sb + 64u * SSTR * 4u, B + (size_t)(bn + r0 + 64) * K + k0 + c0 * 4);
        }
        asm volatile("cp.async.commit_group;\n");
    };

    float acc[4][4][4];
#pragma unroll
    for (int mt = 0; mt < 4; mt++)
#pragma unroll
        for (int nt = 0; nt < 4; nt++)
#pragma unroll
            for (int i = 0; i < 4; i++) acc[mt][nt][i] = 0.f;

    issue(0); issue(1); issue(2);

    for (int it = 0; it < niter; it++) {
        asm volatile("cp.async.wait_group 2;\n" ::: "memory");
        __syncthreads();
        issue(it + STAGES - 1);

        const uint32_t* As = sm + (it & (STAGES - 1)) * TILE_U32;
        const uint32_t* Bs = As + STAGES * TILE_U32;

#pragma unroll
        for (int kk = 0; kk < BK; kk += 8) {
            uint32_t af[4][4], bf[4][2];
#pragma unroll
            for (int mt = 0; mt < 4; mt++) {
                int m0 = wm * 64 + mt * 16 + g;
                af[mt][0] = As[m0 * SSTR + kk + ctg];
                af[mt][1] = As[(m0 + 8) * SSTR + kk + ctg];
                af[mt][2] = As[m0 * SSTR + kk + ctg + 4];
                af[mt][3] = As[(m0 + 8) * SSTR + kk + ctg + 4];
            }
#pragma unroll
            for (int nt = 0; nt < 4; nt++) {
                int n0 = wn * 32 + nt * 8 + g;
                bf[nt][0] = Bs[n0 * SSTR + kk + ctg];
                bf[nt][1] = Bs[n0 * SSTR + kk + ctg + 4];
            }
#pragma unroll
            for (int mt = 0; mt < 4; mt++)
#pragma unroll
                for (int nt = 0; nt < 4; nt++)
                    mma_tf32(acc[mt][nt], af[mt], bf[nt]);
        }
    }

#pragma unroll
    for (int mt = 0; mt < 4; mt++) {
        int mrow = bm + wm * 64 + mt * 16 + g;
#pragma unroll
        for (int nt = 0; nt < 4; nt++) {
            int ncol = bn + wn * 32 + nt * 8 + 2 * ctg;
            float2 v0 = make_float2(acc[mt][nt][0], acc[mt][nt][1]);
            float2 v1 = make_float2(acc[mt][nt][2], acc[mt][nt][3]);
            *(float2*)(C + (size_t)mrow * N + ncol) = v0;
            *(float2*)(C + (size_t)(mrow + 8) * N + ncol) = v1;
        }
    }
}

// Fused Q/K/V projection: blockIdx.x in [0,24) selects target GEMM.
__global__ __launch_bounds__(256) void gemm_qkv(
    const uint32_t* __restrict__ A,
    const uint32_t* __restrict__ Bq, const uint32_t* __restrict__ Bk,
    const uint32_t* __restrict__ Bv,
    float* __restrict__ Cq, float* __restrict__ Ck, float* __restrict__ Cv)
{
    extern __shared__ uint32_t sm[];
    int bx = blockIdx.x;
    int bm = blockIdx.y * BM;
    if (bx < 16)      gemm_body(A, Bq, Cq, QDIM, HIDDEN, bm, bx * BM, sm);
    else if (bx < 20) gemm_body(A, Bk, Ck, KVDIM, HIDDEN, bm, (bx - 16) * BM, sm);
    else              gemm_body(A, Bv, Cv, KVDIM, HIDDEN, bm, (bx - 20) * BM, sm);
}

__global__ __launch_bounds__(256) void gemm_o(
    const uint32_t* __restrict__ A, const uint32_t* __restrict__ B,
    float* __restrict__ C)
{
    extern __shared__ uint32_t sm[];
    gemm_body(A, B, C, HIDDEN, QDIM, blockIdx.y * BM, blockIdx.x * BM, sm);
}

// ---------------------------------------------------------------------------
// RoPE in place on X[S, nheads*HD].
// ---------------------------------------------------------------------------
__global__ void rope_kernel(float* __restrict__ X, int nheads, int total)
{
    int idx = blockIdx.x * blockDim.x + threadIdx.x;
    if (idx >= total) return;
    int j = idx & (HD / 2 - 1);
    int h = (idx >> 5) % nheads;
    int s = idx / ((HD / 2) * nheads);

    float invf = exp2f(-13.2877123795494f * (float)(2 * j) / (float)HD);
    float ang = (float)s * invf;
    float sn, cs;
    sincosf(ang, &sn, &cs);

    float* p = X + (size_t)s * nheads * HD + h * HD + j;
    float x1 = p[0];
    float x2 = p[HD / 2];
    p[0]      = x1 * cs - x2 * sn;
    p[HD / 2] = x2 * cs + x1 * sn;
}

// ---------------------------------------------------------------------------
// Tensor-core causal flash attention with GQA (tf32 mma).
// Grid: (SQ/128, NH). Block: 256 threads = 8 warps. KV tiles of 64.
// Output written tf32-pre-rounded for the O projection.
// ---------------------------------------------------------------------------
#define KSTR 68
#define VSTR 72
#define PSTR 68
#define ATT_SMEM_U32 (64 * KSTR + 64 * VSTR + 128 * PSTR)

__global__ __launch_bounds__(256) void flash_attn_tc(
    const float* __restrict__ Q, const float* __restrict__ K,
    const float* __restrict__ V, float* __restrict__ O)
{
    extern __shared__ uint32_t sm[];
    uint32_t* Ks  = sm;
    uint32_t* Vs  = sm + 64 * KSTR;
    uint32_t* QPs = sm + 64 * KSTR + 64 * VSTR;

    const int qt  = blockIdx.x;
    const int h   = blockIdx.y;
    const int kvh = h >> 2;
    const int tid = threadIdx.x;
    const int wid = tid >> 5;
    const int lane = tid & 31;
    const int g = lane >> 2;
    const int ctg = lane & 3;
    const int lrow0 = wid * 16 + g;
    const int grow0 = qt * 128 + lrow0;
    const int grow1 = grow0 + 8;

    for (int i = tid; i < 128 * 16; i += 256) {
        int r = i >> 4, c4 = i & 15;
        float4 v = *(const float4*)(Q + (size_t)(qt * 128 + r) * QDIM + h * HD + c4 * 4);
        uint32_t* p = QPs + r * PSTR + c4 * 4;
        p[0] = f2tf32(v.x * 0.125f);
        p[1] = f2tf32(v.y * 0.125f);
        p[2] = f2tf32(v.z * 0.125f);
        p[3] = f2tf32(v.w * 0.125f);
    }
    __syncthreads();

    uint32_t qf[8][4];
#pragma unroll
    for (int a = 0; a < 8; a++) {
        qf[a][0] = QPs[lrow0 * PSTR + a * 8 + ctg];
        qf[a][1] = QPs[(lrow0 + 8) * PSTR + a * 8 + ctg];
        qf[a][2] = QPs[lrow0 * PSTR + a * 8 + ctg + 4];
        qf[a][3] = QPs[(lrow0 + 8) * PSTR + a * 8 + ctg + 4];
    }
    __syncthreads();

    float acc[8][4];
#pragma unroll
    for (int nt = 0; nt < 8; nt++)
#pragma unroll
        for (int i = 0; i < 4; i++) acc[nt][i] = 0.f;
    float m0 = -1e30f, m1 = -1e30f, l0 = 0.f, l1 = 0.f;

    const int ntiles = 2 * qt + 2;
    for (int kt = 0; kt < ntiles; kt++) {
        for (int i = tid; i < 64 * 16; i += 256) {
            int r = i >> 4, c4 = i & 15;
            size_t goff = (size_t)(kt * 64 + r) * KVDIM + kvh * HD + c4 * 4;
            float4 kv = *(const float4*)(K + goff);
            uint32_t* pk = Ks + r * KSTR + c4 * 4;
            pk[0] = f2tf32(kv.x); pk[1] = f2tf32(kv.y);
            pk[2] = f2tf32(kv.z); pk[3] = f2tf32(kv.w);
            float4 vv = *(const float4*)(V + goff);
            uint32_t* pv = Vs + r * VSTR + c4 * 4;
            pv[0] = f2tf32(vv.x); pv[1] = f2tf32(vv.y);
            pv[2] = f2tf32(vv.z); pv[3] = f2tf32(vv.w);
        }
        __syncthreads();

        float sc[8][4];
#pragma unroll
        for (int nt = 0; nt < 8; nt++)
#pragma unroll
            for (int i = 0; i < 4; i++) sc[nt][i] = 0.f;

#pragma unroll
        for (int kk = 0; kk < 8; kk++) {
#pragma unroll
            for (int nt = 0; nt < 8; nt++) {
                uint32_t b[2];
                b[0] = Ks[(nt * 8 + g) * KSTR + kk * 8 + ctg];
                b[1] = Ks[(nt * 8 + g) * KSTR + kk * 8 + ctg + 4];
                mma_tf32(sc[nt], qf[kk], b);
            }
        }

        if (kt >= 2 * qt) {
#pragma unroll
            for (int nt = 0; nt < 8; nt++) {
                int col = kt * 64 + nt * 8 + 2 * ctg;
                if (col > grow0)     sc[nt][0] = -1e30f;
                if (col + 1 > grow0) sc[nt][1] = -1e30f;
                if (col > grow1)     sc[nt][2] = -1e30f;
                if (col + 1 > grow1) sc[nt][3] = -1e30f;
            }
        }

        float tmax0 = -1e30f, tmax1 = -1e30f;
#pragma unroll
        for (int nt = 0; nt < 8; nt++) {
            tmax0 = fmaxf(tmax0, fmaxf(sc[nt][0], sc[nt][1]));
            tmax1 = fmaxf(tmax1, fmaxf(sc[nt][2], sc[nt][3]));
        }
#pragma unroll
        for (int off = 1; off <= 2; off <<= 1) {
            tmax0 = fmaxf(tmax0, __shfl_xor_sync(0xffffffffu, tmax0, off));
            tmax1 = fmaxf(tmax1, __shfl_xor_sync(0xffffffffu, tmax1, off));
        }
        float m0n = fmaxf(m0, tmax0);
        float m1n = fmaxf(m1, tmax1);
        float corr0 = __expf(m0 - m0n);
        float corr1 = __expf(m1 - m1n);
        m0 = m0n; m1 = m1n;

        float sum0 = 0.f, sum1 = 0.f;
#pragma unroll
        for (int nt = 0; nt < 8; nt++) {
            float p0 = __expf(sc[nt][0] - m0);
            float p1 = __expf(sc[nt][1] - m0);
            float p2 = __expf(sc[nt][2] - m1);
            float p3 = __expf(sc[nt][3] - m1);
            sum0 += p0 + p1;
            sum1 += p2 + p3;
            sc[nt][0] = p0; sc[nt][1] = p1; sc[nt][2] = p2; sc[nt][3] = p3;
        }
#pragma unroll
        for (int off = 1; off <= 2; off <<= 1) {
            sum0 += __shfl_xor_sync(0xffffffffu, sum0, off);
            sum1 += __shfl_xor_sync(0xffffffffu, sum1, off);
        }
        l0 = l0 * corr0 + sum0;
        l1 = l1 * corr1 + sum1;
#pragma unroll
        for (int nt = 0; nt < 8; nt++) {
            acc[nt][0] *= corr0; acc[nt][1] *= corr0;
            acc[nt][2] *= corr1; acc[nt][3] *= corr1;
        }

#pragma unroll
        for (int nt = 0; nt < 8; nt++) {
            uint32_t* p0 = QPs + lrow0 * PSTR + nt * 8 + 2 * ctg;
            p0[0] = f2tf32(sc[nt][0]);
            p0[1] = f2tf32(sc[nt][1]);
            uint32_t* p1 = QPs + (lrow0 + 8) * PSTR + nt * 8 + 2 * ctg;
            p1[0] = f2tf32(sc[nt][2]);
            p1[1] = f2tf32(sc[nt][3]);
        }
        __syncwarp();

#pragma unroll
        for (int j8 = 0; j8 < 8; j8++) {
            uint32_t a[4];
            a[0] = QPs[lrow0 * PSTR + j8 * 8 + ctg];
            a[1] = QPs[(lrow0 + 8) * PSTR + j8 * 8 + ctg];
            a[2] = QPs[lrow0 * PSTR + j8 * 8 + ctg + 4];
            a[3] = QPs[(lrow0 + 8) * PSTR + j8 * 8 + ctg + 4];
#pragma unroll
            for (int nt = 0; nt < 8; nt++) {
                uint32_t b[2];
                b[0] = Vs[(j8 * 8 + ctg) * VSTR + nt * 8 + g];
                b[1] = Vs[(j8 * 8 + ctg + 4) * VSTR + nt * 8 + g];
                mma_tf32(acc[nt], a, b);
            }
        }
        __syncwarp();
        __syncthreads();
    }

    float inv0 = 1.f / l0;
    float inv1 = 1.f / l1;
#pragma unroll
    for (int nt = 0; nt < 8; nt++) {
        int col = h * HD + nt * 8 + 2 * ctg;
        float2 v0, v1;
        v0.x = __uint_as_float(f2tf32(acc[nt][0] * inv0));
        v0.y = __uint_as_float(f2tf32(acc[nt][1] * inv0));
        v1.x = __uint_as_float(f2tf32(acc[nt][2] * inv1));
        v1.y = __uint_as_float(f2tf32(acc[nt][3] * inv1));
        *(float2*)(O + (size_t)grow0 * QDIM + col) = v0;
        *(float2*)(O + (size_t)grow1 * QDIM + col) = v1;
    }
}

// ---------------------------------------------------------------------------
extern "C" void kernel_launch(void* const* d_in, const int* in_sizes, int n_in,
                              void* d_out, int out_size)
{
    const float* hs = (const float*)d_in[0];
    const float* Wq = (const float*)d_in[1];
    const float* Wk = (const float*)d_in[2];
    const float* Wv = (const float*)d_in[3];
    const float* Wo = (const float*)d_in[4];
    float* out = (float*)d_out;

    float *Qp, *Kp, *Vp, *Op;
    uint32_t *hsT, *WqT, *WkT, *WvT, *WoT;
    cudaGetSymbolAddress((void**)&Qp, g_Q);
    cudaGetSymbolAddress((void**)&Kp, g_K);
    cudaGetSymbolAddress((void**)&Vp, g_V);
    cudaGetSymbolAddress((void**)&Op, g_O);
    cudaGetSymbolAddress((void**)&hsT, g_hsT);
    cudaGetSymbolAddress((void**)&WqT, g_WqT);
    cudaGetSymbolAddress((void**)&WkT, g_WkT);
    cudaGetSymbolAddress((void**)&WvT, g_WvT);
    cudaGetSymbolAddress((void**)&WoT, g_WoT);

    static bool attr_done = false;
    if (!attr_done) {
        cudaFuncSetAttribute(flash_attn_tc,
                             cudaFuncAttributeMaxDynamicSharedMemorySize,
                             ATT_SMEM_U32 * 4);
        cudaFuncSetAttribute(gemm_qkv,
                             cudaFuncAttributeMaxDynamicSharedMemorySize,
                             GEMM_SMEM_BYTES);
        cudaFuncSetAttribute(gemm_o,
                             cudaFuncAttributeMaxDynamicSharedMemorySize,
                             GEMM_SMEM_BYTES);
        attr_done = true;
    }

    // fp32 -> tf32 pre-conversion
    {
        const int nb = 256 * 4;
        int n1 = SQ * HIDDEN;
        int n2 = QDIM * HIDDEN;
        int n3 = KVDIM * HIDDEN;
        conv_tf32<<<(n1 + nb - 1) / nb, 256>>>(hs, hsT, n1);
        conv_tf32<<<(n2 + nb - 1) / nb, 256>>>(Wq, WqT, n2);
        conv_tf32<<<(n3 + nb - 1) / nb, 256>>>(Wk, WkT, n3);
        conv_tf32<<<(n3 + nb - 1) / nb, 256>>>(Wv, WvT, n3);
        conv_tf32<<<(n2 + nb - 1) / nb, 256>>>(Wo, WoT, n2);
    }

    // fused QKV projection (24 x 16 blocks)
    gemm_qkv<<<dim3(24, 16), 256, GEMM_SMEM_BYTES>>>(hsT, WqT, WkT, WvT, Qp, Kp, Vp);

    // RoPE
    {
        int totq = SQ * NH * (HD / 2);
        int totk = SQ * NKV * (HD / 2);
        rope_kernel<<<(totq + 255) / 256, 256>>>(Qp, NH, totq);
        rope_kernel<<<(totk + 255) / 256, 256>>>(Kp, NKV, totk);
    }

    // attention (writes tf32-rounded O)
    flash_attn_tc<<<dim3(SQ / 128, NH), 256, ATT_SMEM_U32 * 4>>>(Qp, Kp, Vp, Op);

    // output projection
    gemm_o<<<dim3(16, 16), 256, GEMM_SMEM_BYTES>>>((const uint32_t*)Op, WoT, out);
}

// round 6
// speedup vs baseline: 4.9529x; 1.0950x over previous
#include <cuda_runtime.h>
#include <math.h>
#include <stdint.h>

#define SQ     2048
#define HIDDEN 2048
#define NH     32
#define NKV    8
#define HD     64
#define QDIM   (NH * HD)    // 2048
#define KVDIM  (NKV * HD)   // 512

__device__ float    g_Q[(size_t)SQ * QDIM];
__device__ float    g_K[(size_t)SQ * KVDIM];
__device__ float    g_V[(size_t)SQ * KVDIM];
__device__ float    g_O[(size_t)SQ * QDIM];      // tf32-rounded bits
__device__ uint32_t g_hsT[(size_t)SQ * HIDDEN];
__device__ uint32_t g_WqT[(size_t)QDIM * HIDDEN];
__device__ uint32_t g_WkT[(size_t)KVDIM * HIDDEN];
__device__ uint32_t g_WvT[(size_t)KVDIM * HIDDEN];
__device__ uint32_t g_WoT[(size_t)HIDDEN * QDIM];

__device__ __forceinline__ uint32_t f2tf32(float x) {
    uint32_t u;
    asm("cvt.rna.tf32.f32 %0, %1;" : "=r"(u) : "f"(x));
    return u;
}

__device__ __forceinline__ void mma_tf32(float* d, const uint32_t* a, const uint32_t* b) {
    asm volatile(
        "mma.sync.aligned.m16n8k8.row.col.f32.tf32.tf32.f32 "
        "{%0,%1,%2,%3}, {%4,%5,%6,%7}, {%8,%9}, {%0,%1,%2,%3};\n"
        : "+f"(d[0]), "+f"(d[1]), "+f"(d[2]), "+f"(d[3])
        : "r"(a[0]), "r"(a[1]), "r"(a[2]), "r"(a[3]), "r"(b[0]), "r"(b[1]));
}

// ---------------------------------------------------------------------------
// Fused fp32 -> tf32(RNA) conversion for all 5 tensors.
// ---------------------------------------------------------------------------
#define N_HS (SQ * HIDDEN)       // 4M
#define N_WQ (QDIM * HIDDEN)     // 4M
#define N_WK (KVDIM * HIDDEN)    // 1M
#define CONV_TOTAL (N_HS + N_WQ + 2 * N_WK + N_WQ)

__global__ void conv_all(
    const float* __restrict__ hs, const float* __restrict__ Wq,
    const float* __restrict__ Wk, const float* __restrict__ Wv,
    const float* __restrict__ Wo,
    uint32_t* __restrict__ hsT, uint32_t* __restrict__ WqT,
    uint32_t* __restrict__ WkT, uint32_t* __restrict__ WvT,
    uint32_t* __restrict__ WoT)
{
    long long i = (long long)(blockIdx.x * blockDim.x + threadIdx.x) * 4;
    if (i >= CONV_TOTAL) return;
    const float* src;
    uint32_t* dst;
    long long off = i;
    if (off < N_HS)                     { src = hs; dst = hsT; }
    else if ((off -= N_HS) < N_WQ)      { src = Wq; dst = WqT; }
    else if ((off -= N_WQ) < N_WK)      { src = Wk; dst = WkT; }
    else if ((off -= N_WK) < N_WK)      { src = Wv; dst = WvT; }
    else { off -= N_WK;                   src = Wo; dst = WoT; }

    float4 v = *(const float4*)(src + off);
    uint4 o;
    o.x = f2tf32(v.x); o.y = f2tf32(v.y);
    o.z = f2tf32(v.z); o.w = f2tf32(v.w);
    *(uint4*)(dst + off) = o;
}

// ---------------------------------------------------------------------------
// tf32 GEMM v3: C[M,N] = A[M,K]*B[N,K]^T. 128x128 block, BK=16, 4 stages,
// 128 threads = 4 warps (2x2), warp tile 64x64. 2 CTAs/SM.
// ---------------------------------------------------------------------------
#define BM 128
#define BN 128
#define BK 16
#define SSTR 20
#define STAGES 4
#define TILE_U32 (BM * SSTR)
#define GEMM_SMEM_BYTES (2 * STAGES * TILE_U32 * 4)   // 80 KB

__device__ __forceinline__ void cp16(uint32_t saddr, const void* g) {
    asm volatile("cp.async.cg.shared.global [%0], [%1], 16;\n" :: "r"(saddr), "l"(g));
}

__device__ __forceinline__ void gemm_body(
    const uint32_t* __restrict__ A, const uint32_t* __restrict__ B,
    float* __restrict__ C, int N, int K, int bm, int bn, uint32_t* sm)
{
    const int tid = threadIdx.x;
    const int wid = tid >> 5, lane = tid & 31;
    const int g = lane >> 2, ctg = lane & 3;
    const int wm = wid & 1, wn = wid >> 1;
    const int niter = K / BK;

    const uint32_t sbase = (uint32_t)__cvta_generic_to_shared(sm);

    auto issue = [&](int it) {
        if (it < niter) {
            int st = it & (STAGES - 1);
            int k0 = it * BK;
#pragma unroll
            for (int s = 0; s < 4; s++) {
                int slot = tid + s * 128;
                int r = slot >> 2, c = slot & 3;
                uint32_t sa = sbase + (uint32_t)(st * TILE_U32 + r * SSTR + c * 4) * 4u;
                cp16(sa, A + (size_t)(bm + r) * K + k0 + c * 4);
                cp16(sa + (uint32_t)(STAGES * TILE_U32) * 4u,
                     B + (size_t)(bn + r) * K + k0 + c * 4);
            }
        }
        asm volatile("cp.async.commit_group;\n");
    };

    float acc[4][8][4];
#pragma unroll
    for (int mt = 0; mt < 4; mt++)
#pragma unroll
        for (int nt = 0; nt < 8; nt++)
#pragma unroll
            for (int i = 0; i < 4; i++) acc[mt][nt][i] = 0.f;

    issue(0); issue(1); issue(2);

    for (int it = 0; it < niter; it++) {
        asm volatile("cp.async.wait_group 2;\n" ::: "memory");
        __syncthreads();
        issue(it + STAGES - 1);

        const uint32_t* As = sm + (it & (STAGES - 1)) * TILE_U32;
        const uint32_t* Bs = As + STAGES * TILE_U32;

#pragma unroll
        for (int kk = 0; kk < BK; kk += 8) {
            uint32_t af[4][4], bf[8][2];
#pragma unroll
            for (int mt = 0; mt < 4; mt++) {
                int m0 = wm * 64 + mt * 16 + g;
                af[mt][0] = As[m0 * SSTR + kk + ctg];
                af[mt][1] = As[(m0 + 8) * SSTR + kk + ctg];
                af[mt][2] = As[m0 * SSTR + kk + ctg + 4];
                af[mt][3] = As[(m0 + 8) * SSTR + kk + ctg + 4];
            }
#pragma unroll
            for (int nt = 0; nt < 8; nt++) {
                int n0 = wn * 64 + nt * 8 + g;
                bf[nt][0] = Bs[n0 * SSTR + kk + ctg];
                bf[nt][1] = Bs[n0 * SSTR + kk + ctg + 4];
            }
#pragma unroll
            for (int mt = 0; mt < 4; mt++)
#pragma unroll
                for (int nt = 0; nt < 8; nt++)
                    mma_tf32(acc[mt][nt], af[mt], bf[nt]);
        }
    }

#pragma unroll
    for (int mt = 0; mt < 4; mt++) {
        int mrow = bm + wm * 64 + mt * 16 + g;
#pragma unroll
        for (int nt = 0; nt < 8; nt++) {
            int ncol = bn + wn * 64 + nt * 8 + 2 * ctg;
            float2 v0 = make_float2(acc[mt][nt][0], acc[mt][nt][1]);
            float2 v1 = make_float2(acc[mt][nt][2], acc[mt][nt][3]);
            *(float2*)(C + (size_t)mrow * N + ncol) = v0;
            *(float2*)(C + (size_t)(mrow + 8) * N + ncol) = v1;
        }
    }
}

// Fused Q/K/V projection: blockIdx.x in [0,24) selects target GEMM.
__global__ __launch_bounds__(128) void gemm_qkv(
    const uint32_t* __restrict__ A,
    const uint32_t* __restrict__ Bq, const uint32_t* __restrict__ Bk,
    const uint32_t* __restrict__ Bv,
    float* __restrict__ Cq, float* __restrict__ Ck, float* __restrict__ Cv)
{
    extern __shared__ uint32_t sm[];
    int bx = blockIdx.x;
    int bm = blockIdx.y * BM;
    if (bx < 16)      gemm_body(A, Bq, Cq, QDIM, HIDDEN, bm, bx * BM, sm);
    else if (bx < 20) gemm_body(A, Bk, Ck, KVDIM, HIDDEN, bm, (bx - 16) * BM, sm);
    else              gemm_body(A, Bv, Cv, KVDIM, HIDDEN, bm, (bx - 20) * BM, sm);
}

__global__ __launch_bounds__(128) void gemm_o(
    const uint32_t* __restrict__ A, const uint32_t* __restrict__ B,
    float* __restrict__ C)
{
    extern __shared__ uint32_t sm[];
    gemm_body(A, B, C, HIDDEN, QDIM, blockIdx.y * BM, blockIdx.x * BM, sm);
}

// ---------------------------------------------------------------------------
// RoPE in place on X[S, nheads*HD].
// ---------------------------------------------------------------------------
__global__ void rope_kernel(float* __restrict__ X, int nheads, int total)
{
    int idx = blockIdx.x * blockDim.x + threadIdx.x;
    if (idx >= total) return;
    int j = idx & (HD / 2 - 1);
    int h = (idx >> 5) % nheads;
    int s = idx / ((HD / 2) * nheads);

    float invf = exp2f(-13.2877123795494f * (float)(2 * j) / (float)HD);
    float ang = (float)s * invf;
    float sn, cs;
    sincosf(ang, &sn, &cs);

    float* p = X + (size_t)s * nheads * HD + h * HD + j;
    float x1 = p[0];
    float x2 = p[HD / 2];
    p[0]      = x1 * cs - x2 * sn;
    p[HD / 2] = x2 * cs + x1 * sn;
}

// ---------------------------------------------------------------------------
// Tensor-core causal flash attention with GQA (tf32 mma).
// Grid: (SQ/128, NH). Block: 256 threads = 8 warps. KV tiles of 64.
// ---------------------------------------------------------------------------
#define KSTR 68
#define VSTR 72
#define PSTR 68
#define ATT_SMEM_U32 (64 * KSTR + 64 * VSTR + 128 * PSTR)

__global__ __launch_bounds__(256, 2) void flash_attn_tc(
    const float* __restrict__ Q, const float* __restrict__ K,
    const float* __restrict__ V, float* __restrict__ O)
{
    extern __shared__ uint32_t sm[];
    uint32_t* Ks  = sm;
    uint32_t* Vs  = sm + 64 * KSTR;
    uint32_t* QPs = sm + 64 * KSTR + 64 * VSTR;

    const int qt  = blockIdx.x;
    const int h   = blockIdx.y;
    const int kvh = h >> 2;
    const int tid = threadIdx.x;
    const int wid = tid >> 5;
    const int lane = tid & 31;
    const int g = lane >> 2;
    const int ctg = lane & 3;
    const int lrow0 = wid * 16 + g;
    const int grow0 = qt * 128 + lrow0;
    const int grow1 = grow0 + 8;

    for (int i = tid; i < 128 * 16; i += 256) {
        int r = i >> 4, c4 = i & 15;
        float4 v = *(const float4*)(Q + (size_t)(qt * 128 + r) * QDIM + h * HD + c4 * 4);
        uint32_t* p = QPs + r * PSTR + c4 * 4;
        p[0] = f2tf32(v.x * 0.125f);
        p[1] = f2tf32(v.y * 0.125f);
        p[2] = f2tf32(v.z * 0.125f);
        p[3] = f2tf32(v.w * 0.125f);
    }
    __syncthreads();

    uint32_t qf[8][4];
#pragma unroll
    for (int a = 0; a < 8; a++) {
        qf[a][0] = QPs[lrow0 * PSTR + a * 8 + ctg];
        qf[a][1] = QPs[(lrow0 + 8) * PSTR + a * 8 + ctg];
        qf[a][2] = QPs[lrow0 * PSTR + a * 8 + ctg + 4];
        qf[a][3] = QPs[(lrow0 + 8) * PSTR + a * 8 + ctg + 4];
    }
    __syncthreads();

    float acc[8][4];
#pragma unroll
    for (int nt = 0; nt < 8; nt++)
#pragma unroll
        for (int i = 0; i < 4; i++) acc[nt][i] = 0.f;
    float m0 = -1e30f, m1 = -1e30f, l0 = 0.f, l1 = 0.f;

    const int ntiles = 2 * qt + 2;
    for (int kt = 0; kt < ntiles; kt++) {
        for (int i = tid; i < 64 * 16; i += 256) {
            int r = i >> 4, c4 = i & 15;
            size_t goff = (size_t)(kt * 64 + r) * KVDIM + kvh * HD + c4 * 4;
            float4 kv = *(const float4*)(K + goff);
            uint32_t* pk = Ks + r * KSTR + c4 * 4;
            pk[0] = f2tf32(kv.x); pk[1] = f2tf32(kv.y);
            pk[2] = f2tf32(kv.z); pk[3] = f2tf32(kv.w);
            float4 vv = *(const float4*)(V + goff);
            uint32_t* pv = Vs + r * VSTR + c4 * 4;
            pv[0] = f2tf32(vv.x); pv[1] = f2tf32(vv.y);
            pv[2] = f2tf32(vv.z); pv[3] = f2tf32(vv.w);
        }
        __syncthreads();

        float sc[8][4];
#pragma unroll
        for (int nt = 0; nt < 8; nt++)
#pragma unroll
            for (int i = 0; i < 4; i++) sc[nt][i] = 0.f;

#pragma unroll
        for (int kk = 0; kk < 8; kk++) {
#pragma unroll
            for (int nt = 0; nt < 8; nt++) {
                uint32_t b[2];
                b[0] = Ks[(nt * 8 + g) * KSTR + kk * 8 + ctg];
                b[1] = Ks[(nt * 8 + g) * KSTR + kk * 8 + ctg + 4];
                mma_tf32(sc[nt], qf[kk], b);
            }
        }

        if (kt >= 2 * qt) {
#pragma unroll
            for (int nt = 0; nt < 8; nt++) {
                int col = kt * 64 + nt * 8 + 2 * ctg;
                if (col > grow0)     sc[nt][0] = -1e30f;
                if (col + 1 > grow0) sc[nt][1] = -1e30f;
                if (col > grow1)     sc[nt][2] = -1e30f;
                if (col + 1 > grow1) sc[nt][3] = -1e30f;
            }
        }

        float tmax0 = -1e30f, tmax1 = -1e30f;
#pragma unroll
        for (int nt = 0; nt < 8; nt++) {
            tmax0 = fmaxf(tmax0, fmaxf(sc[nt][0], sc[nt][1]));
            tmax1 = fmaxf(tmax1, fmaxf(sc[nt][2], sc[nt][3]));
        }
#pragma unroll
        for (int off = 1; off <= 2; off <<= 1) {
            tmax0 = fmaxf(tmax0, __shfl_xor_sync(0xffffffffu, tmax0, off));
            tmax1 = fmaxf(tmax1, __shfl_xor_sync(0xffffffffu, tmax1, off));
        }
        float m0n = fmaxf(m0, tmax0);
        float m1n = fmaxf(m1, tmax1);
        float corr0 = __expf(m0 - m0n);
        float corr1 = __expf(m1 - m1n);
        m0 = m0n; m1 = m1n;

        float sum0 = 0.f, sum1 = 0.f;
#pragma unroll
        for (int nt = 0; nt < 8; nt++) {
            float p0 = __expf(sc[nt][0] - m0);
            float p1 = __expf(sc[nt][1] - m0);
            float p2 = __expf(sc[nt][2] - m1);
            float p3 = __expf(sc[nt][3] - m1);
            sum0 += p0 + p1;
            sum1 += p2 + p3;
            sc[nt][0] = p0; sc[nt][1] = p1; sc[nt][2] = p2; sc[nt][3] = p3;
        }
#pragma unroll
        for (int off = 1; off <= 2; off <<= 1) {
            sum0 += __shfl_xor_sync(0xffffffffu, sum0, off);
            sum1 += __shfl_xor_sync(0xffffffffu, sum1, off);
        }
        l0 = l0 * corr0 + sum0;
        l1 = l1 * corr1 + sum1;
#pragma unroll
        for (int nt = 0; nt < 8; nt++) {
            acc[nt][0] *= corr0; acc[nt][1] *= corr0;
            acc[nt][2] *= corr1; acc[nt][3] *= corr1;
        }

#pragma unroll
        for (int nt = 0; nt < 8; nt++) {
            uint32_t* p0 = QPs + lrow0 * PSTR + nt * 8 + 2 * ctg;
            p0[0] = f2tf32(sc[nt][0]);
            p0[1] = f2tf32(sc[nt][1]);
            uint32_t* p1 = QPs + (lrow0 + 8) * PSTR + nt * 8 + 2 * ctg;
            p1[0] = f2tf32(sc[nt][2]);
            p1[1] = f2tf32(sc[nt][3]);
        }
        __syncwarp();

#pragma unroll
        for (int j8 = 0; j8 < 8; j8++) {
            uint32_t a[4];
            a[0] = QPs[lrow0 * PSTR + j8 * 8 + ctg];
            a[1] = QPs[(lrow0 + 8) * PSTR + j8 * 8 + ctg];
            a[2] = QPs[lrow0 * PSTR + j8 * 8 + ctg + 4];
            a[3] = QPs[(lrow0 + 8) * PSTR + j8 * 8 + ctg + 4];
#pragma unroll
            for (int nt = 0; nt < 8; nt++) {
                uint32_t b[2];
                b[0] = Vs[(j8 * 8 + ctg) * VSTR + nt * 8 + g];
                b[1] = Vs[(j8 * 8 + ctg + 4) * VSTR + nt * 8 + g];
                mma_tf32(acc[nt], a, b);
            }
        }
        __syncwarp();
        __syncthreads();
    }

    float inv0 = 1.f / l0;
    float inv1 = 1.f / l1;
#pragma unroll
    for (int nt = 0; nt < 8; nt++) {
        int col = h * HD + nt * 8 + 2 * ctg;
        float2 v0, v1;
        v0.x = __uint_as_float(f2tf32(acc[nt][0] * inv0));
        v0.y = __uint_as_float(f2tf32(acc[nt][1] * inv0));
        v1.x = __uint_as_float(f2tf32(acc[nt][2] * inv1));
        v1.y = __uint_as_float(f2tf32(acc[nt][3] * inv1));
        *(float2*)(O + (size_t)grow0 * QDIM + col) = v0;
        *(float2*)(O + (size_t)grow1 * QDIM + col) = v1;
    }
}

// ---------------------------------------------------------------------------
extern "C" void kernel_launch(void* const* d_in, const int* in_sizes, int n_in,
                              void* d_out, int out_size)
{
    const float* hs = (const float*)d_in[0];
    const float* Wq = (const float*)d_in[1];
    const float* Wk = (const float*)d_in[2];
    const float* Wv = (const float*)d_in[3];
    const float* Wo = (const float*)d_in[4];
    float* out = (float*)d_out;

    float *Qp, *Kp, *Vp, *Op;
    uint32_t *hsT, *WqT, *WkT, *WvT, *WoT;
    cudaGetSymbolAddress((void**)&Qp, g_Q);
    cudaGetSymbolAddress((void**)&Kp, g_K);
    cudaGetSymbolAddress((void**)&Vp, g_V);
    cudaGetSymbolAddress((void**)&Op, g_O);
    cudaGetSymbolAddress((void**)&hsT, g_hsT);
    cudaGetSymbolAddress((void**)&WqT, g_WqT);
    cudaGetSymbolAddress((void**)&WkT, g_WkT);
    cudaGetSymbolAddress((void**)&WvT, g_WvT);
    cudaGetSymbolAddress((void**)&WoT, g_WoT);

    static bool attr_done = false;
    if (!attr_done) {
        cudaFuncSetAttribute(flash_attn_tc,
                             cudaFuncAttributeMaxDynamicSharedMemorySize,
                             ATT_SMEM_U32 * 4);
        cudaFuncSetAttribute(gemm_qkv,
                             cudaFuncAttributeMaxDynamicSharedMemorySize,
                             GEMM_SMEM_BYTES);
        cudaFuncSetAttribute(gemm_o,
                             cudaFuncAttributeMaxDynamicSharedMemorySize,
                             GEMM_SMEM_BYTES);
        attr_done = true;
    }

    // fused fp32 -> tf32 conversion
    {
        long long nthreads = CONV_TOTAL / 4;
        int nblk = (int)((nthreads + 255) / 256);
        conv_all<<<nblk, 256>>>(hs, Wq, Wk, Wv, Wo, hsT, WqT, WkT, WvT, WoT);
    }

    // fused QKV projection
    gemm_qkv<<<dim3(24, 16), 128, GEMM_SMEM_BYTES>>>(hsT, WqT, WkT, WvT, Qp, Kp, Vp);

    // RoPE
    {
        int totq = SQ * NH * (HD / 2);
        int totk = SQ * NKV * (HD / 2);
        rope_kernel<<<(totq + 255) / 256, 256>>>(Qp, NH, totq);
        rope_kernel<<<(totk + 255) / 256, 256>>>(Kp, NKV, totk);
    }

    // attention
    flash_attn_tc<<<dim3(SQ / 128, NH), 256, ATT_SMEM_U32 * 4>>>(Qp, Kp, Vp, Op);

    // output projection
    gemm_o<<<dim3(16, 16), 128, GEMM_SMEM_BYTES>>>((const uint32_t*)Op, WoT, out);
}

// round 7
// speedup vs baseline: 5.1340x; 1.0366x over previous
#include <cuda_runtime.h>
#include <math.h>
#include <stdint.h>

#define SQ     2048
#define HIDDEN 2048
#define NH     32
#define NKV    8
#define HD     64
#define QDIM   (NH * HD)    // 2048
#define KVDIM  (NKV * HD)   // 512

__device__ float    g_Q[(size_t)SQ * QDIM];
__device__ float    g_K[(size_t)SQ * KVDIM];
__device__ float    g_V[(size_t)SQ * KVDIM];
__device__ float    g_O[(size_t)SQ * QDIM];      // tf32-rounded bits
__device__ uint32_t g_hsT[(size_t)SQ * HIDDEN];
__device__ uint32_t g_WqT[(size_t)QDIM * HIDDEN];
__device__ uint32_t g_WkT[(size_t)KVDIM * HIDDEN];
__device__ uint32_t g_WvT[(size_t)KVDIM * HIDDEN];
__device__ uint32_t g_WoT[(size_t)HIDDEN * QDIM];
__device__ uint32_t g_Qtf[(size_t)SQ * QDIM];    // tf32, roped, pre-scaled
__device__ uint32_t g_Ktf[(size_t)SQ * KVDIM];   // tf32, roped
__device__ uint32_t g_Vtf[(size_t)SQ * KVDIM];   // tf32

__device__ __forceinline__ uint32_t f2tf32(float x) {
    uint32_t u;
    asm("cvt.rna.tf32.f32 %0, %1;" : "=r"(u) : "f"(x));
    return u;
}

__device__ __forceinline__ void mma_tf32(float* d, const uint32_t* a, const uint32_t* b) {
    asm volatile(
        "mma.sync.aligned.m16n8k8.row.col.f32.tf32.tf32.f32 "
        "{%0,%1,%2,%3}, {%4,%5,%6,%7}, {%8,%9}, {%0,%1,%2,%3};\n"
        : "+f"(d[0]), "+f"(d[1]), "+f"(d[2]), "+f"(d[3])
        : "r"(a[0]), "r"(a[1]), "r"(a[2]), "r"(a[3]), "r"(b[0]), "r"(b[1]));
}

__device__ __forceinline__ void cp16(uint32_t saddr, const void* g) {
    asm volatile("cp.async.cg.shared.global [%0], [%1], 16;\n" :: "r"(saddr), "l"(g));
}

// ---------------------------------------------------------------------------
// Fused fp32 -> tf32(RNA) conversion for all 5 input tensors.
// ---------------------------------------------------------------------------
#define N_HS (SQ * HIDDEN)
#define N_WQ (QDIM * HIDDEN)
#define N_WK (KVDIM * HIDDEN)
#define CONV_TOTAL (N_HS + N_WQ + 2 * N_WK + N_WQ)

__global__ void conv_all(
    const float* __restrict__ hs, const float* __restrict__ Wq,
    const float* __restrict__ Wk, const float* __restrict__ Wv,
    const float* __restrict__ Wo,
    uint32_t* __restrict__ hsT, uint32_t* __restrict__ WqT,
    uint32_t* __restrict__ WkT, uint32_t* __restrict__ WvT,
    uint32_t* __restrict__ WoT)
{
    long long i = (long long)(blockIdx.x * blockDim.x + threadIdx.x) * 4;
    if (i >= CONV_TOTAL) return;
    const float* src;
    uint32_t* dst;
    long long off = i;
    if (off < N_HS)                     { src = hs; dst = hsT; }
    else if ((off -= N_HS) < N_WQ)      { src = Wq; dst = WqT; }
    else if ((off -= N_WQ) < N_WK)      { src = Wk; dst = WkT; }
    else if ((off -= N_WK) < N_WK)      { src = Wv; dst = WvT; }
    else { off -= N_WK;                   src = Wo; dst = WoT; }

    float4 v = *(const float4*)(src + off);
    uint4 o;
    o.x = f2tf32(v.x); o.y = f2tf32(v.y);
    o.z = f2tf32(v.z); o.w = f2tf32(v.w);
    *(uint4*)(dst + off) = o;
}

// ---------------------------------------------------------------------------
// tf32 GEMM: 128x128 block, BK=16, 4 stages, 128 threads, warp tile 64x64.
// ---------------------------------------------------------------------------
#define BM 128
#define BN 128
#define BK 16
#define SSTR 20
#define STAGES 4
#define TILE_U32 (BM * SSTR)
#define GEMM_SMEM_BYTES (2 * STAGES * TILE_U32 * 4)   // 80 KB

__device__ __forceinline__ void gemm_body(
    const uint32_t* __restrict__ A, const uint32_t* __restrict__ B,
    float* __restrict__ C, int N, int K, int bm, int bn, uint32_t* sm)
{
    const int tid = threadIdx.x;
    const int wid = tid >> 5, lane = tid & 31;
    const int g = lane >> 2, ctg = lane & 3;
    const int wm = wid & 1, wn = wid >> 1;
    const int niter = K / BK;

    const uint32_t sbase = (uint32_t)__cvta_generic_to_shared(sm);

    auto issue = [&](int it) {
        if (it < niter) {
            int st = it & (STAGES - 1);
            int k0 = it * BK;
#pragma unroll
            for (int s = 0; s < 4; s++) {
                int slot = tid + s * 128;
                int r = slot >> 2, c = slot & 3;
                uint32_t sa = sbase + (uint32_t)(st * TILE_U32 + r * SSTR + c * 4) * 4u;
                cp16(sa, A + (size_t)(bm + r) * K + k0 + c * 4);
                cp16(sa + (uint32_t)(STAGES * TILE_U32) * 4u,
                     B + (size_t)(bn + r) * K + k0 + c * 4);
            }
        }
        asm volatile("cp.async.commit_group;\n");
    };

    float acc[4][8][4];
#pragma unroll
    for (int mt = 0; mt < 4; mt++)
#pragma unroll
        for (int nt = 0; nt < 8; nt++)
#pragma unroll
            for (int i = 0; i < 4; i++) acc[mt][nt][i] = 0.f;

    issue(0); issue(1); issue(2);

    for (int it = 0; it < niter; it++) {
        asm volatile("cp.async.wait_group 2;\n" ::: "memory");
        __syncthreads();
        issue(it + STAGES - 1);

        const uint32_t* As = sm + (it & (STAGES - 1)) * TILE_U32;
        const uint32_t* Bs = As + STAGES * TILE_U32;

#pragma unroll
        for (int kk = 0; kk < BK; kk += 8) {
            uint32_t af[4][4], bf[8][2];
#pragma unroll
            for (int mt = 0; mt < 4; mt++) {
                int m0 = wm * 64 + mt * 16 + g;
                af[mt][0] = As[m0 * SSTR + kk + ctg];
                af[mt][1] = As[(m0 + 8) * SSTR + kk + ctg];
                af[mt][2] = As[m0 * SSTR + kk + ctg + 4];
                af[mt][3] = As[(m0 + 8) * SSTR + kk + ctg + 4];
            }
#pragma unroll
            for (int nt = 0; nt < 8; nt++) {
                int n0 = wn * 64 + nt * 8 + g;
                bf[nt][0] = Bs[n0 * SSTR + kk + ctg];
                bf[nt][1] = Bs[n0 * SSTR + kk + ctg + 4];
            }
#pragma unroll
            for (int mt = 0; mt < 4; mt++)
#pragma unroll
                for (int nt = 0; nt < 8; nt++)
                    mma_tf32(acc[mt][nt], af[mt], bf[nt]);
        }
    }

#pragma unroll
    for (int mt = 0; mt < 4; mt++) {
        int mrow = bm + wm * 64 + mt * 16 + g;
#pragma unroll
        for (int nt = 0; nt < 8; nt++) {
            int ncol = bn + wn * 64 + nt * 8 + 2 * ctg;
            float2 v0 = make_float2(acc[mt][nt][0], acc[mt][nt][1]);
            float2 v1 = make_float2(acc[mt][nt][2], acc[mt][nt][3]);
            *(float2*)(C + (size_t)mrow * N + ncol) = v0;
            *(float2*)(C + (size_t)(mrow + 8) * N + ncol) = v1;
        }
    }
}

__global__ __launch_bounds__(128) void gemm_qkv(
    const uint32_t* __restrict__ A,
    const uint32_t* __restrict__ Bq, const uint32_t* __restrict__ Bk,
    const uint32_t* __restrict__ Bv,
    float* __restrict__ Cq, float* __restrict__ Ck, float* __restrict__ Cv)
{
    extern __shared__ uint32_t sm[];
    int bx = blockIdx.x;
    int bm = blockIdx.y * BM;
    if (bx < 16)      gemm_body(A, Bq, Cq, QDIM, HIDDEN, bm, bx * BM, sm);
    else if (bx < 20) gemm_body(A, Bk, Ck, KVDIM, HIDDEN, bm, (bx - 16) * BM, sm);
    else              gemm_body(A, Bv, Cv, KVDIM, HIDDEN, bm, (bx - 20) * BM, sm);
}

__global__ __launch_bounds__(128) void gemm_o(
    const uint32_t* __restrict__ A, const uint32_t* __restrict__ B,
    float* __restrict__ C)
{
    extern __shared__ uint32_t sm[];
    gemm_body(A, B, C, HIDDEN, QDIM, blockIdx.y * BM, blockIdx.x * BM, sm);
}

// ---------------------------------------------------------------------------
// Fused RoPE + tf32 conversion: Q (roped, x0.125), K (roped), V (copy).
// Same fp32 op sequence as before -> bit-identical numerics.
// ---------------------------------------------------------------------------
#define NQ_ROPE (SQ * NH * (HD / 2))
#define NK_ROPE (SQ * NKV * (HD / 2))
#define NV_CONV (SQ * KVDIM / 4)
#define RC_TOTAL (NQ_ROPE + NK_ROPE + NV_CONV)

__global__ void rope_conv(
    const float* __restrict__ Q, const float* __restrict__ K,
    const float* __restrict__ V,
    uint32_t* __restrict__ Qt, uint32_t* __restrict__ Kt,
    uint32_t* __restrict__ Vt)
{
    int idx = blockIdx.x * blockDim.x + threadIdx.x;
    if (idx < NQ_ROPE) {
        int j = idx & 31;
        int h = (idx >> 5) % NH;
        int s = idx / (32 * NH);
        float invf = exp2f(-13.2877123795494f * (float)(2 * j) / (float)HD);
        float sn, cs;
        sincosf((float)s * invf, &sn, &cs);
        size_t o = (size_t)s * QDIM + h * HD + j;
        float x1 = Q[o], x2 = Q[o + 32];
        Qt[o]      = f2tf32((x1 * cs - x2 * sn) * 0.125f);
        Qt[o + 32] = f2tf32((x2 * cs + x1 * sn) * 0.125f);
        return;
    }
    idx -= NQ_ROPE;
    if (idx < NK_ROPE) {
        int j = idx & 31;
        int h = (idx >> 5) % NKV;
        int s = idx / (32 * NKV);
        float invf = exp2f(-13.2877123795494f * (float)(2 * j) / (float)HD);
        float sn, cs;
        sincosf((float)s * invf, &sn, &cs);
        size_t o = (size_t)s * KVDIM + h * HD + j;
        float x1 = K[o], x2 = K[o + 32];
        Kt[o]      = f2tf32(x1 * cs - x2 * sn);
        Kt[o + 32] = f2tf32(x2 * cs + x1 * sn);
        return;
    }
    idx -= NK_ROPE;
    if (idx < NV_CONV) {
        float4 v = ((const float4*)V)[idx];
        uint4 o;
        o.x = f2tf32(v.x); o.y = f2tf32(v.y);
        o.z = f2tf32(v.z); o.w = f2tf32(v.w);
        ((uint4*)Vt)[idx] = o;
    }
}

// ---------------------------------------------------------------------------
// Tensor-core causal flash attention (tf32, pre-converted inputs,
// cp.async double-buffered KV tiles).
// Grid: (SQ/128, NH). Block: 256 threads = 8 warps. KV tiles of 64.
// ---------------------------------------------------------------------------
#define KSTR 68
#define VSTR 72
#define PSTR 68
#define KV_STG (64 * KSTR + 64 * VSTR)           // 8960 u32 per stage
#define ATT_SMEM_U32 (2 * KV_STG + 128 * PSTR)   // 26624 u32 = 104 KB

__global__ __launch_bounds__(256, 2) void flash_attn_tc(
    const uint32_t* __restrict__ Q, const uint32_t* __restrict__ K,
    const uint32_t* __restrict__ V, float* __restrict__ O)
{
    extern __shared__ uint32_t sm[];
    uint32_t* QPs = sm + 2 * KV_STG;

    const int qt  = blockIdx.x;
    const int h   = blockIdx.y;
    const int kvh = h >> 2;
    const int tid = threadIdx.x;
    const int wid = tid >> 5;
    const int lane = tid & 31;
    const int g = lane >> 2;
    const int ctg = lane & 3;
    const int lrow0 = wid * 16 + g;
    const int grow0 = qt * 128 + lrow0;
    const int grow1 = grow0 + 8;
    const int ntiles = 2 * qt + 2;

    const uint32_t sbase = (uint32_t)__cvta_generic_to_shared(sm);

    auto issue = [&](int kt) {
        if (kt < ntiles) {
            int st = kt & 1;
            uint32_t kdst = sbase + (uint32_t)(st * KV_STG) * 4u;
            uint32_t vdst = kdst + (uint32_t)(64 * KSTR) * 4u;
#pragma unroll
            for (int s = 0; s < 4; s++) {
                int i = tid + s * 256;
                int r = i >> 4, c4 = i & 15;
                size_t goff = (size_t)(kt * 64 + r) * KVDIM + kvh * HD + c4 * 4;
                cp16(kdst + (uint32_t)(r * KSTR + c4 * 4) * 4u, K + goff);
                cp16(vdst + (uint32_t)(r * VSTR + c4 * 4) * 4u, V + goff);
            }
        }
        asm volatile("cp.async.commit_group;\n");
    };

    // Kick off first two KV tiles, then stage Q while they fly.
    issue(0);
    issue(1);

    for (int i = tid; i < 128 * 16; i += 256) {
        int r = i >> 4, c4 = i & 15;
        uint4 v = *(const uint4*)(Q + (size_t)(qt * 128 + r) * QDIM + h * HD + c4 * 4);
        *(uint4*)(QPs + r * PSTR + c4 * 4) = v;
    }
    __syncthreads();

    uint32_t qf[8][4];
#pragma unroll
    for (int a = 0; a < 8; a++) {
        qf[a][0] = QPs[lrow0 * PSTR + a * 8 + ctg];
        qf[a][1] = QPs[(lrow0 + 8) * PSTR + a * 8 + ctg];
        qf[a][2] = QPs[lrow0 * PSTR + a * 8 + ctg + 4];
        qf[a][3] = QPs[(lrow0 + 8) * PSTR + a * 8 + ctg + 4];
    }
    __syncthreads();   // QPs free for P

    float acc[8][4];
#pragma unroll
    for (int nt = 0; nt < 8; nt++)
#pragma unroll
        for (int i = 0; i < 4; i++) acc[nt][i] = 0.f;
    float m0 = -1e30f, m1 = -1e30f, l0 = 0.f, l1 = 0.f;

    for (int kt = 0; kt < ntiles; kt++) {
        // tile kt ready when <=1 group outstanding (the kt+1 group)
        asm volatile("cp.async.wait_group 1;\n" ::: "memory");
        __syncthreads();

        const uint32_t* Ks = sm + (kt & 1) * KV_STG;
        const uint32_t* Vs = Ks + 64 * KSTR;

        // ---- S = Q K^T
        float sc[8][4];
#pragma unroll
        for (int nt = 0; nt < 8; nt++)
#pragma unroll
            for (int i = 0; i < 4; i++) sc[nt][i] = 0.f;

#pragma unroll
        for (int kk = 0; kk < 8; kk++) {
#pragma unroll
            for (int nt = 0; nt < 8; nt++) {
                uint32_t b[2];
                b[0] = Ks[(nt * 8 + g) * KSTR + kk * 8 + ctg];
                b[1] = Ks[(nt * 8 + g) * KSTR + kk * 8 + ctg + 4];
                mma_tf32(sc[nt], qf[kk], b);
            }
        }

        if (kt >= 2 * qt) {
#pragma unroll
            for (int nt = 0; nt < 8; nt++) {
                int col = kt * 64 + nt * 8 + 2 * ctg;
                if (col > grow0)     sc[nt][0] = -1e30f;
                if (col + 1 > grow0) sc[nt][1] = -1e30f;
                if (col > grow1)     sc[nt][2] = -1e30f;
                if (col + 1 > grow1) sc[nt][3] = -1e30f;
            }
        }

        // ---- online softmax
        float tmax0 = -1e30f, tmax1 = -1e30f;
#pragma unroll
        for (int nt = 0; nt < 8; nt++) {
            tmax0 = fmaxf(tmax0, fmaxf(sc[nt][0], sc[nt][1]));
            tmax1 = fmaxf(tmax1, fmaxf(sc[nt][2], sc[nt][3]));
        }
#pragma unroll
        for (int off = 1; off <= 2; off <<= 1) {
            tmax0 = fmaxf(tmax0, __shfl_xor_sync(0xffffffffu, tmax0, off));
            tmax1 = fmaxf(tmax1, __shfl_xor_sync(0xffffffffu, tmax1, off));
        }
        float m0n = fmaxf(m0, tmax0);
        float m1n = fmaxf(m1, tmax1);
        float corr0 = __expf(m0 - m0n);
        float corr1 = __expf(m1 - m1n);
        m0 = m0n; m1 = m1n;

        float sum0 = 0.f, sum1 = 0.f;
#pragma unroll
        for (int nt = 0; nt < 8; nt++) {
            float p0 = __expf(sc[nt][0] - m0);
            float p1 = __expf(sc[nt][1] - m0);
            float p2 = __expf(sc[nt][2] - m1);
            float p3 = __expf(sc[nt][3] - m1);
            sum0 += p0 + p1;
            sum1 += p2 + p3;
            sc[nt][0] = p0; sc[nt][1] = p1; sc[nt][2] = p2; sc[nt][3] = p3;
        }
#pragma unroll
        for (int off = 1; off <= 2; off <<= 1) {
            sum0 += __shfl_xor_sync(0xffffffffu, sum0, off);
            sum1 += __shfl_xor_sync(0xffffffffu, sum1, off);
        }
        l0 = l0 * corr0 + sum0;
        l1 = l1 * corr1 + sum1;
#pragma unroll
        for (int nt = 0; nt < 8; nt++) {
            acc[nt][0] *= corr0; acc[nt][1] *= corr0;
            acc[nt][2] *= corr1; acc[nt][3] *= corr1;
        }

        // ---- P -> smem (per-warp region)
#pragma unroll
        for (int nt = 0; nt < 8; nt++) {
            uint32_t* p0 = QPs + lrow0 * PSTR + nt * 8 + 2 * ctg;
            p0[0] = f2tf32(sc[nt][0]);
            p0[1] = f2tf32(sc[nt][1]);
            uint32_t* p1 = QPs + (lrow0 + 8) * PSTR + nt * 8 + 2 * ctg;
            p1[0] = f2tf32(sc[nt][2]);
            p1[1] = f2tf32(sc[nt][3]);
        }
        __syncwarp();

        // ---- O += P V
#pragma unroll
        for (int j8 = 0; j8 < 8; j8++) {
            uint32_t a[4];
            a[0] = QPs[lrow0 * PSTR + j8 * 8 + ctg];
            a[1] = QPs[(lrow0 + 8) * PSTR + j8 * 8 + ctg];
            a[2] = QPs[lrow0 * PSTR + j8 * 8 + ctg + 4];
            a[3] = QPs[(lrow0 + 8) * PSTR + j8 * 8 + ctg + 4];
#pragma unroll
            for (int nt = 0; nt < 8; nt++) {
                uint32_t b[2];
                b[0] = Vs[(j8 * 8 + ctg) * VSTR + nt * 8 + g];
                b[1] = Vs[(j8 * 8 + ctg + 4) * VSTR + nt * 8 + g];
                mma_tf32(acc[nt], a, b);
            }
        }
        __syncthreads();     // stage (kt&1) free for tile kt+2
        issue(kt + 2);
    }

    float inv0 = 1.f / l0;
    float inv1 = 1.f / l1;
#pragma unroll
    for (int nt = 0; nt < 8; nt++) {
        int col = h * HD + nt * 8 + 2 * ctg;
        float2 v0, v1;
        v0.x = __uint_as_float(f2tf32(acc[nt][0] * inv0));
        v0.y = __uint_as_float(f2tf32(acc[nt][1] * inv0));
        v1.x = __uint_as_float(f2tf32(acc[nt][2] * inv1));
        v1.y = __uint_as_float(f2tf32(acc[nt][3] * inv1));
        *(float2*)(O + (size_t)grow0 * QDIM + col) = v0;
        *(float2*)(O + (size_t)grow1 * QDIM + col) = v1;
    }
}

// ---------------------------------------------------------------------------
extern "C" void kernel_launch(void* const* d_in, const int* in_sizes, int n_in,
                              void* d_out, int out_size)
{
    const float* hs = (const float*)d_in[0];
    const float* Wq = (const float*)d_in[1];
    const float* Wk = (const float*)d_in[2];
    const float* Wv = (const float*)d_in[3];
    const float* Wo = (const float*)d_in[4];
    float* out = (float*)d_out;

    float *Qp, *Kp, *Vp, *Op;
    uint32_t *hsT, *WqT, *WkT, *WvT, *WoT, *Qtf, *Ktf, *Vtf;
    cudaGetSymbolAddress((void**)&Qp, g_Q);
    cudaGetSymbolAddress((void**)&Kp, g_K);
    cudaGetSymbolAddress((void**)&Vp, g_V);
    cudaGetSymbolAddress((void**)&Op, g_O);
    cudaGetSymbolAddress((void**)&hsT, g_hsT);
    cudaGetSymbolAddress((void**)&WqT, g_WqT);
    cudaGetSymbolAddress((void**)&WkT, g_WkT);
    cudaGetSymbolAddress((void**)&WvT, g_WvT);
    cudaGetSymbolAddress((void**)&WoT, g_WoT);
    cudaGetSymbolAddress((void**)&Qtf, g_Qtf);
    cudaGetSymbolAddress((void**)&Ktf, g_Ktf);
    cudaGetSymbolAddress((void**)&Vtf, g_Vtf);

    static bool attr_done = false;
    if (!attr_done) {
        cudaFuncSetAttribute(flash_attn_tc,
                             cudaFuncAttributeMaxDynamicSharedMemorySize,
                             ATT_SMEM_U32 * 4);
        cudaFuncSetAttribute(gemm_qkv,
                             cudaFuncAttributeMaxDynamicSharedMemorySize,
                             GEMM_SMEM_BYTES);
        cudaFuncSetAttribute(gemm_o,
                             cudaFuncAttributeMaxDynamicSharedMemorySize,
                             GEMM_SMEM_BYTES);
        attr_done = true;
    }

    // fp32 -> tf32 for inputs
    {
        long long nthreads = CONV_TOTAL / 4;
        int nblk = (int)((nthreads + 255) / 256);
        conv_all<<<nblk, 256>>>(hs, Wq, Wk, Wv, Wo, hsT, WqT, WkT, WvT, WoT);
    }

    // fused QKV projection
    gemm_qkv<<<dim3(24, 16), 128, GEMM_SMEM_BYTES>>>(hsT, WqT, WkT, WvT, Qp, Kp, Vp);

    // fused RoPE + tf32 conversion of Q, K, V
    rope_conv<<<(RC_TOTAL + 255) / 256, 256>>>(Qp, Kp, Vp, Qtf, Ktf, Vtf);

    // attention
    flash_attn_tc<<<dim3(SQ / 128, NH), 256, ATT_SMEM_U32 * 4>>>(Qtf, Ktf, Vtf, Op);

    // output projection
    gemm_o<<<dim3(16, 16), 128, GEMM_SMEM_BYTES>>>((const uint32_t*)Op, WoT, out);
}

// round 10
// speedup vs baseline: 5.6508x; 1.1007x over previous
#include <cuda_runtime.h>
#include <math.h>
#include <stdint.h>

#define SQ     2048
#define HIDDEN 2048
#define NH     32
#define NKV    8
#define HD     64
#define QDIM   (NH * HD)    // 2048
#define KVDIM  (NKV * HD)   // 512

__device__ float    g_Q[(size_t)SQ * QDIM];
__device__ float    g_K[(size_t)SQ * KVDIM];
__device__ float    g_V[(size_t)SQ * KVDIM];
__device__ float    g_O[(size_t)SQ * QDIM];      // tf32 bits, pair-interleaved cols
__device__ uint32_t g_hsT[(size_t)SQ * HIDDEN];
__device__ uint32_t g_WqT[(size_t)QDIM * HIDDEN];
__device__ uint32_t g_WkT[(size_t)KVDIM * HIDDEN];
__device__ uint32_t g_WvT[(size_t)KVDIM * HIDDEN];
__device__ uint32_t g_WoT[(size_t)HIDDEN * QDIM];
__device__ uint32_t g_Qtf[(size_t)SQ * QDIM];    // tf32, roped, x0.125, pair-interleaved
__device__ uint32_t g_Ktf[(size_t)SQ * KVDIM];   // tf32, roped, pair-interleaved
__device__ uint32_t g_Vtf[(size_t)SQ * KVDIM];   // tf32, natural

__device__ __forceinline__ uint32_t f2tf32(float x) {
    uint32_t u;
    asm("cvt.rna.tf32.f32 %0, %1;" : "=r"(u) : "f"(x));
    return u;
}

// pair-interleave within 8-col groups: k0,k4,k1,k5,k2,k6,k3,k7
__device__ __forceinline__ int pcol8(int c) {
    return (c & ~7) | (((c & 3) << 1) | ((c >> 2) & 1));
}

__device__ __forceinline__ void mma_tf32(float* d, const uint32_t* a, const uint32_t* b) {
    asm volatile(
        "mma.sync.aligned.m16n8k8.row.col.f32.tf32.tf32.f32 "
        "{%0,%1,%2,%3}, {%4,%5,%6,%7}, {%8,%9}, {%0,%1,%2,%3};\n"
        : "+f"(d[0]), "+f"(d[1]), "+f"(d[2]), "+f"(d[3])
        : "r"(a[0]), "r"(a[1]), "r"(a[2]), "r"(a[3]), "r"(b[0]), "r"(b[1]));
}

__device__ __forceinline__ void cp16(uint32_t saddr, const void* g) {
    asm volatile("cp.async.cg.shared.global [%0], [%1], 16;\n" :: "r"(saddr), "l"(g));
}

// ---------------------------------------------------------------------------
// Fused fp32 -> tf32(RNA) conversion + K-dim pair-interleave, all 5 inputs.
// Each thread handles one 8-element group.
// ---------------------------------------------------------------------------
#define N_HS (SQ * HIDDEN)
#define N_WQ (QDIM * HIDDEN)
#define N_WK (KVDIM * HIDDEN)
#define CONV_TOTAL (N_HS + N_WQ + 2 * N_WK + N_WQ)

__global__ void conv_all(
    const float* __restrict__ hs, const float* __restrict__ Wq,
    const float* __restrict__ Wk, const float* __restrict__ Wv,
    const float* __restrict__ Wo,
    uint32_t* __restrict__ hsT, uint32_t* __restrict__ WqT,
    uint32_t* __restrict__ WkT, uint32_t* __restrict__ WvT,
    uint32_t* __restrict__ WoT)
{
    long long i = (long long)(blockIdx.x * blockDim.x + threadIdx.x) * 8;
    if (i >= CONV_TOTAL) return;
    const float* src;
    uint32_t* dst;
    long long off = i;
    if (off < N_HS)                     { src = hs; dst = hsT; }
    else if ((off -= N_HS) < N_WQ)      { src = Wq; dst = WqT; }
    else if ((off -= N_WQ) < N_WK)      { src = Wk; dst = WkT; }
    else if ((off -= N_WK) < N_WK)      { src = Wv; dst = WvT; }
    else { off -= N_WK;                   src = Wo; dst = WoT; }

    float4 v0 = *(const float4*)(src + off);
    float4 v1 = *(const float4*)(src + off + 4);
    uint4 o0, o1;
    o0.x = f2tf32(v0.x); o0.y = f2tf32(v1.x);
    o0.z = f2tf32(v0.y); o0.w = f2tf32(v1.y);
    o1.x = f2tf32(v0.z); o1.y = f2tf32(v1.z);
    o1.z = f2tf32(v0.w); o1.w = f2tf32(v1.w);
    *(uint4*)(dst + off)     = o0;
    *(uint4*)(dst + off + 4) = o1;
}

// ---------------------------------------------------------------------------
// tf32 GEMM (pair-interleaved operands): 128x128 block, BK=16, 4 stages,
// 128 threads, warp tile 64x64. Fragment loads are LDS.64, conflict-free.
// ---------------------------------------------------------------------------
#define BM 128
#define BN 128
#define BK 16
#define SSTR 24      // 24 % 32 == 24 -> conflict-free 64-bit frag loads
#define STAGES 4
#define TILE_U32 (BM * SSTR)
#define GEMM_SMEM_BYTES (2 * STAGES * TILE_U32 * 4)   // 96 KB

__device__ __forceinline__ void gemm_body(
    const uint32_t* __restrict__ A, const uint32_t* __restrict__ B,
    float* __restrict__ C, int N, int K, int bm, int bn, uint32_t* sm)
{
    const int tid = threadIdx.x;
    const int wid = tid >> 5, lane = tid & 31;
    const int g = lane >> 2, ctg = lane & 3;
    const int wm = wid & 1, wn = wid >> 1;
    const int niter = K / BK;

    const uint32_t sbase = (uint32_t)__cvta_generic_to_shared(sm);

    auto issue = [&](int it) {
        if (it < niter) {
            int st = it & (STAGES - 1);
            int k0 = it * BK;
#pragma unroll
            for (int s = 0; s < 4; s++) {
                int slot = tid + s * 128;
                int r = slot >> 2, c = slot & 3;
                uint32_t sa = sbase + (uint32_t)(st * TILE_U32 + r * SSTR + c * 4) * 4u;
                cp16(sa, A + (size_t)(bm + r) * K + k0 + c * 4);
                cp16(sa + (uint32_t)(STAGES * TILE_U32) * 4u,
                     B + (size_t)(bn + r) * K + k0 + c * 4);
            }
        }
        asm volatile("cp.async.commit_group;\n");
    };

    float acc[4][8][4];
#pragma unroll
    for (int mt = 0; mt < 4; mt++)
#pragma unroll
        for (int nt = 0; nt < 8; nt++)
#pragma unroll
            for (int i = 0; i < 4; i++) acc[mt][nt][i] = 0.f;

    issue(0); issue(1); issue(2);

    for (int it = 0; it < niter; it++) {
        asm volatile("cp.async.wait_group 2;\n" ::: "memory");
        __syncthreads();
        issue(it + STAGES - 1);

        const uint32_t* As = sm + (it & (STAGES - 1)) * TILE_U32;
        const uint32_t* Bs = As + STAGES * TILE_U32;

#pragma unroll
        for (int kk = 0; kk < BK; kk += 8) {
            uint32_t af[4][4], bf[8][2];
#pragma unroll
            for (int mt = 0; mt < 4; mt++) {
                int m0 = wm * 64 + mt * 16 + g;
                uint2 t0 = *(const uint2*)&As[m0 * SSTR + kk + 2 * ctg];
                uint2 t1 = *(const uint2*)&As[(m0 + 8) * SSTR + kk + 2 * ctg];
                af[mt][0] = t0.x; af[mt][2] = t0.y;
                af[mt][1] = t1.x; af[mt][3] = t1.y;
            }
#pragma unroll
            for (int nt = 0; nt < 8; nt++) {
                int n0 = wn * 64 + nt * 8 + g;
                uint2 tb = *(const uint2*)&Bs[n0 * SSTR + kk + 2 * ctg];
                bf[nt][0] = tb.x; bf[nt][1] = tb.y;
            }
#pragma unroll
            for (int mt = 0; mt < 4; mt++)
#pragma unroll
                for (int nt = 0; nt < 8; nt++)
                    mma_tf32(acc[mt][nt], af[mt], bf[nt]);
        }
    }

#pragma unroll
    for (int mt = 0; mt < 4; mt++) {
        int mrow = bm + wm * 64 + mt * 16 + g;
#pragma unroll
        for (int nt = 0; nt < 8; nt++) {
            int ncol = bn + wn * 64 + nt * 8 + 2 * ctg;
            float2 v0 = make_float2(acc[mt][nt][0], acc[mt][nt][1]);
            float2 v1 = make_float2(acc[mt][nt][2], acc[mt][nt][3]);
            *(float2*)(C + (size_t)mrow * N + ncol) = v0;
            *(float2*)(C + (size_t)(mrow + 8) * N + ncol) = v1;
        }
    }
}

__global__ __launch_bounds__(128) void gemm_qkv(
    const uint32_t* __restrict__ A,
    const uint32_t* __restrict__ Bq, const uint32_t* __restrict__ Bk,
    const uint32_t* __restrict__ Bv,
    float* __restrict__ Cq, float* __restrict__ Ck, float* __restrict__ Cv)
{
    extern __shared__ uint32_t sm[];
    int bx = blockIdx.x;
    int bm = blockIdx.y * BM;
    if (bx < 16)      gemm_body(A, Bq, Cq, QDIM, HIDDEN, bm, bx * BM, sm);
    else if (bx < 20) gemm_body(A, Bk, Ck, KVDIM, HIDDEN, bm, (bx - 16) * BM, sm);
    else              gemm_body(A, Bv, Cv, KVDIM, HIDDEN, bm, (bx - 20) * BM, sm);
}

__global__ __launch_bounds__(128) void gemm_o(
    const uint32_t* __restrict__ A, const uint32_t* __restrict__ B,
    float* __restrict__ C)
{
    extern __shared__ uint32_t sm[];
    gemm_body(A, B, C, HIDDEN, QDIM, blockIdx.y * BM, blockIdx.x * BM, sm);
}

// ---------------------------------------------------------------------------
// Fused RoPE + tf32 + pair-interleave: Q (roped, x0.125), K (roped), V (copy,
// natural layout). Same fp32 op sequence -> bit-identical numerics.
// ---------------------------------------------------------------------------
#define NQ_ROPE (SQ * NH * (HD / 2))
#define NK_ROPE (SQ * NKV * (HD / 2))
#define NV_CONV (SQ * KVDIM / 4)
#define RC_TOTAL (NQ_ROPE + NK_ROPE + NV_CONV)

__global__ void rope_conv(
    const float* __restrict__ Q, const float* __restrict__ K,
    const float* __restrict__ V,
    uint32_t* __restrict__ Qt, uint32_t* __restrict__ Kt,
    uint32_t* __restrict__ Vt)
{
    int idx = blockIdx.x * blockDim.x + threadIdx.x;
    if (idx < NQ_ROPE) {
        int j = idx & 31;
        int h = (idx >> 5) % NH;
        int s = idx / (32 * NH);
        float invf = exp2f(-13.2877123795494f * (float)(2 * j) / (float)HD);
        float sn, cs;
        sincosf((float)s * invf, &sn, &cs);
        size_t ob = (size_t)s * QDIM + h * HD;
        float x1 = Q[ob + j], x2 = Q[ob + j + 32];
        Qt[ob + pcol8(j)]      = f2tf32((x1 * cs - x2 * sn) * 0.125f);
        Qt[ob + pcol8(j + 32)] = f2tf32((x2 * cs + x1 * sn) * 0.125f);
        return;
    }
    idx -= NQ_ROPE;
    if (idx < NK_ROPE) {
        int j = idx & 31;
        int h = (idx >> 5) % NKV;
        int s = idx / (32 * NKV);
        float invf = exp2f(-13.2877123795494f * (float)(2 * j) / (float)HD);
        float sn, cs;
        sincosf((float)s * invf, &sn, &cs);
        size_t ob = (size_t)s * KVDIM + h * HD;
        float x1 = K[ob + j], x2 = K[ob + j + 32];
        Kt[ob + pcol8(j)]      = f2tf32(x1 * cs - x2 * sn);
        Kt[ob + pcol8(j + 32)] = f2tf32(x2 * cs + x1 * sn);
        return;
    }
    idx -= NK_ROPE;
    if (idx < NV_CONV) {
        float4 v = ((const float4*)V)[idx];
        uint4 o;
        o.x = f2tf32(v.x); o.y = f2tf32(v.y);
        o.z = f2tf32(v.z); o.w = f2tf32(v.w);
        ((uint4*)Vt)[idx] = o;
    }
}

// ---------------------------------------------------------------------------
// Tensor-core causal flash attention (tf32, pair-interleaved Q/K/P,
// cp.async double-buffered KV, LDS.64 fragment loads, reversed qt order).
// Grid: (SQ/128, NH). Block: 256 threads = 8 warps. KV tiles of 64.
// ---------------------------------------------------------------------------
#define KSTR 72      // 72 % 32 == 8 -> conflict-free 64-bit B-frag loads
#define VSTR 72      // scalar V loads: 8*ctg+g all distinct
#define PSTR 72
#define KV_STG (64 * KSTR + 64 * VSTR)             // 9216 u32 per stage
#define ATT_SMEM_U32 (2 * KV_STG + 128 * PSTR)     // 27648 u32 = 108 KB

__global__ __launch_bounds__(256, 2) void flash_attn_tc(
    const uint32_t* __restrict__ Q, const uint32_t* __restrict__ K,
    const uint32_t* __restrict__ V, float* __restrict__ O)
{
    extern __shared__ uint32_t sm[];
    uint32_t* QPs = sm + 2 * KV_STG;

    const int qt  = gridDim.x - 1 - blockIdx.x;   // heaviest tiles first
    const int h   = blockIdx.y;
    const int kvh = h >> 2;
    const int tid = threadIdx.x;
    const int wid = tid >> 5;
    const int lane = tid & 31;
    const int g = lane >> 2;
    const int ctg = lane & 3;
    const int lrow0 = wid * 16 + g;
    const int grow0 = qt * 128 + lrow0;
    const int grow1 = grow0 + 8;
    const int ntiles = 2 * qt + 2;
    // permuted in-group positions for P stores (cols 2ctg, 2ctg+1)
    const int pc0 = (((2 * ctg) & 3) << 1) | (((2 * ctg) >> 2) & 1);
    const int pc1 = (((2 * ctg + 1) & 3) << 1) | (((2 * ctg + 1) >> 2) & 1);

    const uint32_t sbase = (uint32_t)__cvta_generic_to_shared(sm);

    auto issue = [&](int kt) {
        if (kt < ntiles) {
            int st = kt & 1;
            uint32_t kdst = sbase + (uint32_t)(st * KV_STG) * 4u;
            uint32_t vdst = kdst + (uint32_t)(64 * KSTR) * 4u;
#pragma unroll
            for (int s = 0; s < 4; s++) {
                int i = tid + s * 256;
                int r = i >> 4, c4 = i & 15;
                size_t goff = (size_t)(kt * 64 + r) * KVDIM + kvh * HD + c4 * 4;
                cp16(kdst + (uint32_t)(r * KSTR + c4 * 4) * 4u, K + goff);
                cp16(vdst + (uint32_t)(r * VSTR + c4 * 4) * 4u, V + goff);
            }
        }
        asm volatile("cp.async.commit_group;\n");
    };

    issue(0);
    issue(1);

    for (int i = tid; i < 128 * 16; i += 256) {
        int r = i >> 4, c4 = i & 15;
        uint4 v = *(const uint4*)(Q + (size_t)(qt * 128 + r) * QDIM + h * HD + c4 * 4);
        *(uint4*)(QPs + r * PSTR + c4 * 4) = v;
    }
    __syncthreads();

    uint32_t qf[8][4];
#pragma unroll
    for (int a = 0; a < 8; a++) {
        uint2 t0 = *(const uint2*)&QPs[lrow0 * PSTR + a * 8 + 2 * ctg];
        uint2 t1 = *(const uint2*)&QPs[(lrow0 + 8) * PSTR + a * 8 + 2 * ctg];
        qf[a][0] = t0.x; qf[a][2] = t0.y;
        qf[a][1] = t1.x; qf[a][3] = t1.y;
    }
    __syncthreads();   // QPs free for P

    float acc[8][4];
#pragma unroll
    for (int nt = 0; nt < 8; nt++)
#pragma unroll
        for (int i = 0; i < 4; i++) acc[nt][i] = 0.f;
    float m0 = -1e30f, m1 = -1e30f, l0 = 0.f, l1 = 0.f;

    for (int kt = 0; kt < ntiles; kt++) {
        asm volatile("cp.async.wait_group 1;\n" ::: "memory");
        __syncthreads();

        const uint32_t* Ks = sm + (kt & 1) * KV_STG;
        const uint32_t* Vs = Ks + 64 * KSTR;

        // ---- S = Q K^T
        float sc[8][4];
#pragma unroll
        for (int nt = 0; nt < 8; nt++)
#pragma unroll
            for (int i = 0; i < 4; i++) sc[nt][i] = 0.f;

#pragma unroll
        for (int kk = 0; kk < 8; kk++) {
#pragma unroll
            for (int nt = 0; nt < 8; nt++) {
                uint2 tb = *(const uint2*)&Ks[(nt * 8 + g) * KSTR + kk * 8 + 2 * ctg];
                uint32_t b[2] = { tb.x, tb.y };
                mma_tf32(sc[nt], qf[kk], b);
            }
        }

        if (kt >= 2 * qt) {
#pragma unroll
            for (int nt = 0; nt < 8; nt++) {
                int col = kt * 64 + nt * 8 + 2 * ctg;
                if (col > grow0)     sc[nt][0] = -1e30f;
                if (col + 1 > grow0) sc[nt][1] = -1e30f;
                if (col > grow1)     sc[nt][2] = -1e30f;
                if (col + 1 > grow1) sc[nt][3] = -1e30f;
            }
        }

        // ---- online softmax
        float tmax0 = -1e30f, tmax1 = -1e30f;
#pragma unroll
        for (int nt = 0; nt < 8; nt++) {
            tmax0 = fmaxf(tmax0, fmaxf(sc[nt][0], sc[nt][1]));
            tmax1 = fmaxf(tmax1, fmaxf(sc[nt][2], sc[nt][3]));
        }
#pragma unroll
        for (int off = 1; off <= 2; off <<= 1) {
            tmax0 = fmaxf(tmax0, __shfl_xor_sync(0xffffffffu, tmax0, off));
            tmax1 = fmaxf(tmax1, __shfl_xor_sync(0xffffffffu, tmax1, off));
        }
        float m0n = fmaxf(m0, tmax0);
        float m1n = fmaxf(m1, tmax1);
        float corr0 = __expf(m0 - m0n);
        float corr1 = __expf(m1 - m1n);
        m0 = m0n; m1 = m1n;

        float sum0 = 0.f, sum1 = 0.f;
#pragma unroll
        for (int nt = 0; nt < 8; nt++) {
            float p0 = __expf(sc[nt][0] - m0);
            float p1 = __expf(sc[nt][1] - m0);
            float p2 = __expf(sc[nt][2] - m1);
            float p3 = __expf(sc[nt][3] - m1);
            sum0 += p0 + p1;
            sum1 += p2 + p3;
            sc[nt][0] = p0; sc[nt][1] = p1; sc[nt][2] = p2; sc[nt][3] = p3;
        }
#pragma unroll
        for (int off = 1; off <= 2; off <<= 1) {
            sum0 += __shfl_xor_sync(0xffffffffu, sum0, off);
            sum1 += __shfl_xor_sync(0xffffffffu, sum1, off);
        }
        l0 = l0 * corr0 + sum0;
        l1 = l1 * corr1 + sum1;
#pragma unroll
        for (int nt = 0; nt < 8; nt++) {
            acc[nt][0] *= corr0; acc[nt][1] *= corr0;
            acc[nt][2] *= corr1; acc[nt][3] *= corr1;
        }

        // ---- P -> smem (pair-interleaved positions, per-warp region)
#pragma unroll
        for (int nt = 0; nt < 8; nt++) {
            QPs[lrow0 * PSTR + nt * 8 + pc0]       = f2tf32(sc[nt][0]);
            QPs[lrow0 * PSTR + nt * 8 + pc1]       = f2tf32(sc[nt][1]);
            QPs[(lrow0 + 8) * PSTR + nt * 8 + pc0] = f2tf32(sc[nt][2]);
            QPs[(lrow0 + 8) * PSTR + nt * 8 + pc1] = f2tf32(sc[nt][3]);
        }
        __syncwarp();

        // ---- O += P V
#pragma unroll
        for (int j8 = 0; j8 < 8; j8++) {
            uint2 t0 = *(const uint2*)&QPs[lrow0 * PSTR + j8 * 8 + 2 * ctg];
            uint2 t1 = *(const uint2*)&QPs[(lrow0 + 8) * PSTR + j8 * 8 + 2 * ctg];
            uint32_t a[4] = { t0.x, t1.x, t0.y, t1.y };
#pragma unroll
            for (int nt = 0; nt < 8; nt++) {
                uint32_t b[2];
                b[0] = Vs[(j8 * 8 + ctg) * VSTR + nt * 8 + g];
                b[1] = Vs[(j8 * 8 + ctg + 4) * VSTR + nt * 8 + g];
                mma_tf32(acc[nt], a, b);
            }
        }
        __syncthreads();
        issue(kt + 2);
    }

    // ---- epilogue: write O pair-interleaved (gemm_o consumes it as A)
    float inv0 = 1.f / l0;
    float inv1 = 1.f / l1;
#pragma unroll
    for (int nt = 0; nt < 8; nt++) {
        int colb = h * HD + nt * 8;
        O[(size_t)grow0 * QDIM + colb + pc0] = __uint_as_float(f2tf32(acc[nt][0] * inv0));
        O[(size_t)grow0 * QDIM + colb + pc1] = __uint_as_float(f2tf32(acc[nt][1] * inv0));
        O[(size_t)grow1 * QDIM + colb + pc0] = __uint_as_float(f2tf32(acc[nt][2] * inv1));
        O[(size_t)grow1 * QDIM + colb + pc1] = __uint_as_float(f2tf32(acc[nt][3] * inv1));
    }
}

// ---------------------------------------------------------------------------
extern "C" void kernel_launch(void* const* d_in, const int* in_sizes, int n_in,
                              void* d_out, int out_size)
{
    const float* hs = (const float*)d_in[0];
    const float* Wq = (const float*)d_in[1];
    const float* Wk = (const float*)d_in[2];
    const float* Wv = (const float*)d_in[3];
    const float* Wo = (const float*)d_in[4];
    float* out = (float*)d_out;

    float *Qp, *Kp, *Vp, *Op;
    uint32_t *hsT, *WqT, *WkT, *WvT, *WoT, *Qtf, *Ktf, *Vtf;
    cudaGetSymbolAddress((void**)&Qp, g_Q);
    cudaGetSymbolAddress((void**)&Kp, g_K);
    cudaGetSymbolAddress((void**)&Vp, g_V);
    cudaGetSymbolAddress((void**)&Op, g_O);
    cudaGetSymbolAddress((void**)&hsT, g_hsT);
    cudaGetSymbolAddress((void**)&WqT, g_WqT);
    cudaGetSymbolAddress((void**)&WkT, g_WkT);
    cudaGetSymbolAddress((void**)&WvT, g_WvT);
    cudaGetSymbolAddress((void**)&WoT, g_WoT);
    cudaGetSymbolAddress((void**)&Qtf, g_Qtf);
    cudaGetSymbolAddress((void**)&Ktf, g_Ktf);
    cudaGetSymbolAddress((void**)&Vtf, g_Vtf);

    static bool attr_done = false;
    if (!attr_done) {
        cudaFuncSetAttribute(flash_attn_tc,
                             cudaFuncAttributeMaxDynamicSharedMemorySize,
                             ATT_SMEM_U32 * 4);
        cudaFuncSetAttribute(gemm_qkv,
                             cudaFuncAttributeMaxDynamicSharedMemorySize,
                             GEMM_SMEM_BYTES);
        cudaFuncSetAttribute(gemm_o,
                             cudaFuncAttributeMaxDynamicSharedMemorySize,
                             GEMM_SMEM_BYTES);
        attr_done = true;
    }

    // fp32 -> tf32 + pair-interleave for inputs
    {
        long long nthreads = CONV_TOTAL / 8;
        int nblk = (int)((nthreads + 255) / 256);
        conv_all<<<nblk, 256>>>(hs, Wq, Wk, Wv, Wo, hsT, WqT, WkT, WvT, WoT);
    }

    // fused QKV projection
    gemm_qkv<<<dim3(24, 16), 128, GEMM_SMEM_BYTES>>>(hsT, WqT, WkT, WvT, Qp, Kp, Vp);

    // fused RoPE + tf32 + pair-interleave of Q, K; V convert
    rope_conv<<<(RC_TOTAL + 255) / 256, 256>>>(Qp, Kp, Vp, Qtf, Ktf, Vtf);

    // attention
    flash_attn_tc<<<dim3(SQ / 128, NH), 256, ATT_SMEM_U32 * 4>>>(Qtf, Ktf, Vtf, Op);

    // output projection
    gemm_o<<<dim3(16, 16), 128, GEMM_SMEM_BYTES>>>((const uint32_t*)Op, WoT, out);
}

// round 11
// speedup vs baseline: 5.7626x; 1.0198x over previous
#include <cuda_runtime.h>
#include <math.h>
#include <stdint.h>

#define SQ     2048
#define HIDDEN 2048
#define NH     32
#define NKV    8
#define HD     64
#define QDIM   (NH * HD)    // 2048
#define KVDIM  (NKV * HD)   // 512

__device__ float    g_Q[(size_t)SQ * QDIM];
__device__ float    g_K[(size_t)SQ * KVDIM];
__device__ float    g_V[(size_t)SQ * KVDIM];
__device__ float    g_O[(size_t)SQ * QDIM];      // tf32 bits, pair-interleaved cols
__device__ uint32_t g_hsT[(size_t)SQ * HIDDEN];
__device__ uint32_t g_WqT[(size_t)QDIM * HIDDEN];
__device__ uint32_t g_WkT[(size_t)KVDIM * HIDDEN];
__device__ uint32_t g_WvT[(size_t)KVDIM * HIDDEN];
__device__ uint32_t g_WoT[(size_t)HIDDEN * QDIM];
__device__ uint32_t g_Qtf[(size_t)SQ * QDIM];    // tf32, roped, x0.125, pair-interleaved
__device__ uint32_t g_Ktf[(size_t)SQ * KVDIM];   // tf32, roped, pair-interleaved
__device__ uint32_t g_Vtf[(size_t)NKV * HD * SQ]; // tf32, TRANSPOSED [kvh][d][seq], seq-interleaved

__device__ __forceinline__ uint32_t f2tf32(float x) {
    uint32_t u;
    asm("cvt.rna.tf32.f32 %0, %1;" : "=r"(u) : "f"(x));
    return u;
}

// pair-interleave within 8-groups: 0,4,1,5,2,6,3,7
__device__ __forceinline__ int pcol8(int c) {
    return (c & ~7) | (((c & 3) << 1) | ((c >> 2) & 1));
}

__device__ __forceinline__ void mma_tf32(float* d, const uint32_t* a, const uint32_t* b) {
    asm volatile(
        "mma.sync.aligned.m16n8k8.row.col.f32.tf32.tf32.f32 "
        "{%0,%1,%2,%3}, {%4,%5,%6,%7}, {%8,%9}, {%0,%1,%2,%3};\n"
        : "+f"(d[0]), "+f"(d[1]), "+f"(d[2]), "+f"(d[3])
        : "r"(a[0]), "r"(a[1]), "r"(a[2]), "r"(a[3]), "r"(b[0]), "r"(b[1]));
}

__device__ __forceinline__ void cp16(uint32_t saddr, const void* g) {
    asm volatile("cp.async.cg.shared.global [%0], [%1], 16;\n" :: "r"(saddr), "l"(g));
}

// ---------------------------------------------------------------------------
// Fused fp32 -> tf32(RNA) conversion + K-dim pair-interleave, all 5 inputs.
// ---------------------------------------------------------------------------
#define N_HS (SQ * HIDDEN)
#define N_WQ (QDIM * HIDDEN)
#define N_WK (KVDIM * HIDDEN)
#define CONV_TOTAL (N_HS + N_WQ + 2 * N_WK + N_WQ)

__global__ void conv_all(
    const float* __restrict__ hs, const float* __restrict__ Wq,
    const float* __restrict__ Wk, const float* __restrict__ Wv,
    const float* __restrict__ Wo,
    uint32_t* __restrict__ hsT, uint32_t* __restrict__ WqT,
    uint32_t* __restrict__ WkT, uint32_t* __restrict__ WvT,
    uint32_t* __restrict__ WoT)
{
    long long i = (long long)(blockIdx.x * blockDim.x + threadIdx.x) * 8;
    if (i >= CONV_TOTAL) return;
    const float* src;
    uint32_t* dst;
    long long off = i;
    if (off < N_HS)                     { src = hs; dst = hsT; }
    else if ((off -= N_HS) < N_WQ)      { src = Wq; dst = WqT; }
    else if ((off -= N_WQ) < N_WK)      { src = Wk; dst = WkT; }
    else if ((off -= N_WK) < N_WK)      { src = Wv; dst = WvT; }
    else { off -= N_WK;                   src = Wo; dst = WoT; }

    float4 v0 = *(const float4*)(src + off);
    float4 v1 = *(const float4*)(src + off + 4);
    uint4 o0, o1;
    o0.x = f2tf32(v0.x); o0.y = f2tf32(v1.x);
    o0.z = f2tf32(v0.y); o0.w = f2tf32(v1.y);
    o1.x = f2tf32(v0.z); o1.y = f2tf32(v1.z);
    o1.z = f2tf32(v0.w); o1.w = f2tf32(v1.w);
    *(uint4*)(dst + off)     = o0;
    *(uint4*)(dst + off + 4) = o1;
}

// ---------------------------------------------------------------------------
// tf32 GEMM (pair-interleaved operands): 128x128 block, BK=16, 4 stages,
// 128 threads, warp tile 64x64, LDS.64 fragment loads.
// ---------------------------------------------------------------------------
#define BM 128
#define BN 128
#define BK 16
#define SSTR 24
#define STAGES 4
#define TILE_U32 (BM * SSTR)
#define GEMM_SMEM_BYTES (2 * STAGES * TILE_U32 * 4)   // 96 KB

__device__ __forceinline__ void gemm_body(
    const uint32_t* __restrict__ A, const uint32_t* __restrict__ B,
    float* __restrict__ C, int N, int K, int bm, int bn, uint32_t* sm)
{
    const int tid = threadIdx.x;
    const int wid = tid >> 5, lane = tid & 31;
    const int g = lane >> 2, ctg = lane & 3;
    const int wm = wid & 1, wn = wid >> 1;
    const int niter = K / BK;

    const uint32_t sbase = (uint32_t)__cvta_generic_to_shared(sm);

    auto issue = [&](int it) {
        if (it < niter) {
            int st = it & (STAGES - 1);
            int k0 = it * BK;
#pragma unroll
            for (int s = 0; s < 4; s++) {
                int slot = tid + s * 128;
                int r = slot >> 2, c = slot & 3;
                uint32_t sa = sbase + (uint32_t)(st * TILE_U32 + r * SSTR + c * 4) * 4u;
                cp16(sa, A + (size_t)(bm + r) * K + k0 + c * 4);
                cp16(sa + (uint32_t)(STAGES * TILE_U32) * 4u,
                     B + (size_t)(bn + r) * K + k0 + c * 4);
            }
        }
        asm volatile("cp.async.commit_group;\n");
    };

    float acc[4][8][4];
#pragma unroll
    for (int mt = 0; mt < 4; mt++)
#pragma unroll
        for (int nt = 0; nt < 8; nt++)
#pragma unroll
            for (int i = 0; i < 4; i++) acc[mt][nt][i] = 0.f;

    issue(0); issue(1); issue(2);

    for (int it = 0; it < niter; it++) {
        asm volatile("cp.async.wait_group 2;\n" ::: "memory");
        __syncthreads();
        issue(it + STAGES - 1);

        const uint32_t* As = sm + (it & (STAGES - 1)) * TILE_U32;
        const uint32_t* Bs = As + STAGES * TILE_U32;

#pragma unroll
        for (int kk = 0; kk < BK; kk += 8) {
            uint32_t af[4][4], bf[8][2];
#pragma unroll
            for (int mt = 0; mt < 4; mt++) {
                int m0 = wm * 64 + mt * 16 + g;
                uint2 t0 = *(const uint2*)&As[m0 * SSTR + kk + 2 * ctg];
                uint2 t1 = *(const uint2*)&As[(m0 + 8) * SSTR + kk + 2 * ctg];
                af[mt][0] = t0.x; af[mt][2] = t0.y;
                af[mt][1] = t1.x; af[mt][3] = t1.y;
            }
#pragma unroll
            for (int nt = 0; nt < 8; nt++) {
                int n0 = wn * 64 + nt * 8 + g;
                uint2 tb = *(const uint2*)&Bs[n0 * SSTR + kk + 2 * ctg];
                bf[nt][0] = tb.x; bf[nt][1] = tb.y;
            }
#pragma unroll
            for (int mt = 0; mt < 4; mt++)
#pragma unroll
                for (int nt = 0; nt < 8; nt++)
                    mma_tf32(acc[mt][nt], af[mt], bf[nt]);
        }
    }

#pragma unroll
    for (int mt = 0; mt < 4; mt++) {
        int mrow = bm + wm * 64 + mt * 16 + g;
#pragma unroll
        for (int nt = 0; nt < 8; nt++) {
            int ncol = bn + wn * 64 + nt * 8 + 2 * ctg;
            float2 v0 = make_float2(acc[mt][nt][0], acc[mt][nt][1]);
            float2 v1 = make_float2(acc[mt][nt][2], acc[mt][nt][3]);
            *(float2*)(C + (size_t)mrow * N + ncol) = v0;
            *(float2*)(C + (size_t)(mrow + 8) * N + ncol) = v1;
        }
    }
}

__global__ __launch_bounds__(128) void gemm_qkv(
    const uint32_t* __restrict__ A,
    const uint32_t* __restrict__ Bq, const uint32_t* __restrict__ Bk,
    const uint32_t* __restrict__ Bv,
    float* __restrict__ Cq, float* __restrict__ Ck, float* __restrict__ Cv)
{
    extern __shared__ uint32_t sm[];
    int bx = blockIdx.x;
    int bm = blockIdx.y * BM;
    if (bx < 16)      gemm_body(A, Bq, Cq, QDIM, HIDDEN, bm, bx * BM, sm);
    else if (bx < 20) gemm_body(A, Bk, Ck, KVDIM, HIDDEN, bm, (bx - 16) * BM, sm);
    else              gemm_body(A, Bv, Cv, KVDIM, HIDDEN, bm, (bx - 20) * BM, sm);
}

__global__ __launch_bounds__(128) void gemm_o(
    const uint32_t* __restrict__ A, const uint32_t* __restrict__ B,
    float* __restrict__ C)
{
    extern __shared__ uint32_t sm[];
    gemm_body(A, B, C, HIDDEN, QDIM, blockIdx.y * BM, blockIdx.x * BM, sm);
}

// ---------------------------------------------------------------------------
// Fused RoPE + tf32 + pair-interleave for Q (x0.125) and K.
// ---------------------------------------------------------------------------
#define NQ_ROPE (SQ * NH * (HD / 2))
#define NK_ROPE (SQ * NKV * (HD / 2))
#define RC_TOTAL (NQ_ROPE + NK_ROPE)

__global__ void rope_conv(
    const float* __restrict__ Q, const float* __restrict__ K,
    uint32_t* __restrict__ Qt, uint32_t* __restrict__ Kt)
{
    int idx = blockIdx.x * blockDim.x + threadIdx.x;
    if (idx < NQ_ROPE) {
        int j = idx & 31;
        int h = (idx >> 5) % NH;
        int s = idx / (32 * NH);
        float invf = exp2f(-13.2877123795494f * (float)(2 * j) / (float)HD);
        float sn, cs;
        sincosf((float)s * invf, &sn, &cs);
        size_t ob = (size_t)s * QDIM + h * HD;
        float x1 = Q[ob + j], x2 = Q[ob + j + 32];
        Qt[ob + pcol8(j)]      = f2tf32((x1 * cs - x2 * sn) * 0.125f);
        Qt[ob + pcol8(j + 32)] = f2tf32((x2 * cs + x1 * sn) * 0.125f);
        return;
    }
    idx -= NQ_ROPE;
    if (idx < NK_ROPE) {
        int j = idx & 31;
        int h = (idx >> 5) % NKV;
        int s = idx / (32 * NKV);
        float invf = exp2f(-13.2877123795494f * (float)(2 * j) / (float)HD);
        float sn, cs;
        sincosf((float)s * invf, &sn, &cs);
        size_t ob = (size_t)s * KVDIM + h * HD;
        float x1 = K[ob + j], x2 = K[ob + j + 32];
        Kt[ob + pcol8(j)]      = f2tf32(x1 * cs - x2 * sn);
        Kt[ob + pcol8(j + 32)] = f2tf32(x2 * cs + x1 * sn);
    }
}

// ---------------------------------------------------------------------------
// V transpose + tf32 + seq pair-interleave: Vt[kvh][d][seq'].
// Grid: (SQ/32, NKV), block 256. smem-tiled, fully coalesced both sides.
// ---------------------------------------------------------------------------
__global__ void v_trans(const float* __restrict__ V, uint32_t* __restrict__ Vt)
{
    __shared__ float tile[32][65];
    int s0 = blockIdx.x * 32;
    int kvh = blockIdx.y;
    int tid = threadIdx.x;

    for (int i = tid; i < 32 * 64; i += 256) {
        int r = i >> 6, d = i & 63;
        tile[r][d] = V[(size_t)(s0 + r) * KVDIM + kvh * HD + d];
    }
    __syncthreads();
    for (int i = tid; i < 32 * 64; i += 256) {
        int d = i >> 5, r = i & 31;
        int rp = (r & ~7) | (((r & 3) << 1) | ((r >> 2) & 1));
        Vt[(size_t)kvh * HD * SQ + (size_t)d * SQ + s0 + rp] = f2tf32(tile[r][d]);
    }
}

// ---------------------------------------------------------------------------
// Tensor-core causal flash attention. Q frags direct from gmem; K smem
// seq-major (interleaved d); V smem d-major (interleaved seq) -> all mma
// fragment loads are LDS.64, conflict-free. cp.async double-buffered.
// Grid: (SQ/128, NH) reversed. Block: 256 threads = 8 warps.
// ---------------------------------------------------------------------------
#define KSTR 72
#define VSTR 72
#define PSTR 72
#define KV_STG (64 * KSTR + 64 * VSTR)             // 9216 u32 per stage
#define ATT_SMEM_U32 (2 * KV_STG + 128 * PSTR)     // 27648 u32 = 108 KB

__global__ __launch_bounds__(256, 2) void flash_attn_tc(
    const uint32_t* __restrict__ Q, const uint32_t* __restrict__ K,
    const uint32_t* __restrict__ V, float* __restrict__ O)
{
    extern __shared__ uint32_t sm[];
    uint32_t* QPs = sm + 2 * KV_STG;   // P buffer [128][PSTR]

    const int qt  = gridDim.x - 1 - blockIdx.x;   // heaviest tiles first
    const int h   = blockIdx.y;
    const int kvh = h >> 2;
    const int tid = threadIdx.x;
    const int wid = tid >> 5;
    const int lane = tid & 31;
    const int g = lane >> 2;
    const int ctg = lane & 3;
    const int lrow0 = wid * 16 + g;
    const int grow0 = qt * 128 + lrow0;
    const int grow1 = grow0 + 8;
    const int ntiles = 2 * qt + 2;
    const int pc0 = (((2 * ctg) & 3) << 1) | (((2 * ctg) >> 2) & 1);
    const int pc1 = (((2 * ctg + 1) & 3) << 1) | (((2 * ctg + 1) >> 2) & 1);

    const uint32_t sbase = (uint32_t)__cvta_generic_to_shared(sm);
    const uint32_t* __restrict__ Vh = V + (size_t)kvh * HD * SQ;

    auto issue = [&](int kt) {
        if (kt < ntiles) {
            int st = kt & 1;
            uint32_t kdst = sbase + (uint32_t)(st * KV_STG) * 4u;
            uint32_t vdst = kdst + (uint32_t)(64 * KSTR) * 4u;
#pragma unroll
            for (int s = 0; s < 4; s++) {
                int i = tid + s * 256;
                int r = i >> 4, c4 = i & 15;
                // K: seq-major rows
                cp16(kdst + (uint32_t)(r * KSTR + c4 * 4) * 4u,
                     K + (size_t)(kt * 64 + r) * KVDIM + kvh * HD + c4 * 4);
                // V: d-major rows (transposed layout)
                cp16(vdst + (uint32_t)(r * VSTR + c4 * 4) * 4u,
                     Vh + (size_t)r * SQ + kt * 64 + c4 * 4);
            }
        }
        asm volatile("cp.async.commit_group;\n");
    };

    issue(0);
    issue(1);

    // Q fragments straight from gmem (pair-interleaved layout)
    uint32_t qf[8][4];
#pragma unroll
    for (int a = 0; a < 8; a++) {
        uint2 t0 = *(const uint2*)&Q[(size_t)grow0 * QDIM + h * HD + a * 8 + 2 * ctg];
        uint2 t1 = *(const uint2*)&Q[(size_t)grow1 * QDIM + h * HD + a * 8 + 2 * ctg];
        qf[a][0] = t0.x; qf[a][2] = t0.y;
        qf[a][1] = t1.x; qf[a][3] = t1.y;
    }

    float acc[8][4];
#pragma unroll
    for (int nt = 0; nt < 8; nt++)
#pragma unroll
        for (int i = 0; i < 4; i++) acc[nt][i] = 0.f;
    float m0 = -1e30f, m1 = -1e30f, l0 = 0.f, l1 = 0.f;

    for (int kt = 0; kt < ntiles; kt++) {
        asm volatile("cp.async.wait_group 1;\n" ::: "memory");
        __syncthreads();

        const uint32_t* Ks = sm + (kt & 1) * KV_STG;
        const uint32_t* Vs = Ks + 64 * KSTR;

        // ---- S = Q K^T
        float sc[8][4];
#pragma unroll
        for (int nt = 0; nt < 8; nt++)
#pragma unroll
            for (int i = 0; i < 4; i++) sc[nt][i] = 0.f;

#pragma unroll
        for (int kk = 0; kk < 8; kk++) {
#pragma unroll
            for (int nt = 0; nt < 8; nt++) {
                uint2 tb = *(const uint2*)&Ks[(nt * 8 + g) * KSTR + kk * 8 + 2 * ctg];
                uint32_t b[2] = { tb.x, tb.y };
                mma_tf32(sc[nt], qf[kk], b);
            }
        }

        if (kt >= 2 * qt) {
#pragma unroll
            for (int nt = 0; nt < 8; nt++) {
                int col = kt * 64 + nt * 8 + 2 * ctg;
                if (col > grow0)     sc[nt][0] = -1e30f;
                if (col + 1 > grow0) sc[nt][1] = -1e30f;
                if (col > grow1)     sc[nt][2] = -1e30f;
                if (col + 1 > grow1) sc[nt][3] = -1e30f;
            }
        }

        // ---- online softmax
        float tmax0 = -1e30f, tmax1 = -1e30f;
#pragma unroll
        for (int nt = 0; nt < 8; nt++) {
            tmax0 = fmaxf(tmax0, fmaxf(sc[nt][0], sc[nt][1]));
            tmax1 = fmaxf(tmax1, fmaxf(sc[nt][2], sc[nt][3]));
        }
#pragma unroll
        for (int off = 1; off <= 2; off <<= 1) {
            tmax0 = fmaxf(tmax0, __shfl_xor_sync(0xffffffffu, tmax0, off));
            tmax1 = fmaxf(tmax1, __shfl_xor_sync(0xffffffffu, tmax1, off));
        }
        float m0n = fmaxf(m0, tmax0);
        float m1n = fmaxf(m1, tmax1);
        float corr0 = __expf(m0 - m0n);
        float corr1 = __expf(m1 - m1n);
        m0 = m0n; m1 = m1n;

        float sum0 = 0.f, sum1 = 0.f;
#pragma unroll
        for (int nt = 0; nt < 8; nt++) {
            float p0 = __expf(sc[nt][0] - m0);
            float p1 = __expf(sc[nt][1] - m0);
            float p2 = __expf(sc[nt][2] - m1);
            float p3 = __expf(sc[nt][3] - m1);
            sum0 += p0 + p1;
            sum1 += p2 + p3;
            sc[nt][0] = p0; sc[nt][1] = p1; sc[nt][2] = p2; sc[nt][3] = p3;
        }
#pragma unroll
        for (int off = 1; off <= 2; off <<= 1) {
            sum0 += __shfl_xor_sync(0xffffffffu, sum0, off);
            sum1 += __shfl_xor_sync(0xffffffffu, sum1, off);
        }
        l0 = l0 * corr0 + sum0;
        l1 = l1 * corr1 + sum1;
#pragma unroll
        for (int nt = 0; nt < 8; nt++) {
            acc[nt][0] *= corr0; acc[nt][1] *= corr0;
            acc[nt][2] *= corr1; acc[nt][3] *= corr1;
        }

        // ---- P -> smem (pair-interleaved positions)
#pragma unroll
        for (int nt = 0; nt < 8; nt++) {
            QPs[lrow0 * PSTR + nt * 8 + pc0]       = f2tf32(sc[nt][0]);
            QPs[lrow0 * PSTR + nt * 8 + pc1]       = f2tf32(sc[nt][1]);
            QPs[(lrow0 + 8) * PSTR + nt * 8 + pc0] = f2tf32(sc[nt][2]);
            QPs[(lrow0 + 8) * PSTR + nt * 8 + pc1] = f2tf32(sc[nt][3]);
        }
        __syncwarp();

        // ---- O += P V   (V d-major, seq-interleaved -> LDS.64 B-frags)
#pragma unroll
        for (int j8 = 0; j8 < 8; j8++) {
            uint2 t0 = *(const uint2*)&QPs[lrow0 * PSTR + j8 * 8 + 2 * ctg];
            uint2 t1 = *(const uint2*)&QPs[(lrow0 + 8) * PSTR + j8 * 8 + 2 * ctg];
            uint32_t a[4] = { t0.x, t1.x, t0.y, t1.y };
#pragma unroll
            for (int nt = 0; nt < 8; nt++) {
                uint2 tv = *(const uint2*)&Vs[(nt * 8 + g) * VSTR + j8 * 8 + 2 * ctg];
                uint32_t b[2] = { tv.x, tv.y };
                mma_tf32(acc[nt], a, b);
            }
        }
        __syncthreads();
        issue(kt + 2);
    }

    // ---- epilogue: O pair-interleaved (gemm_o consumes as A)
    float inv0 = 1.f / l0;
    float inv1 = 1.f / l1;
#pragma unroll
    for (int nt = 0; nt < 8; nt++) {
        int colb = h * HD + nt * 8;
        O[(size_t)grow0 * QDIM + colb + pc0] = __uint_as_float(f2tf32(acc[nt][0] * inv0));
        O[(size_t)grow0 * QDIM + colb + pc1] = __uint_as_float(f2tf32(acc[nt][1] * inv0));
        O[(size_t)grow1 * QDIM + colb + pc0] = __uint_as_float(f2tf32(acc[nt][2] * inv1));
        O[(size_t)grow1 * QDIM + colb + pc1] = __uint_as_float(f2tf32(acc[nt][3] * inv1));
    }
}

// ---------------------------------------------------------------------------
extern "C" void kernel_launch(void* const* d_in, const int* in_sizes, int n_in,
                              void* d_out, int out_size)
{
    const float* hs = (const float*)d_in[0];
    const float* Wq = (const float*)d_in[1];
    const float* Wk = (const float*)d_in[2];
    const float* Wv = (const float*)d_in[3];
    const float* Wo = (const float*)d_in[4];
    float* out = (float*)d_out;

    float *Qp, *Kp, *Vp, *Op;
    uint32_t *hsT, *WqT, *WkT, *WvT, *WoT, *Qtf, *Ktf, *Vtf;
    cudaGetSymbolAddress((void**)&Qp, g_Q);
    cudaGetSymbolAddress((void**)&Kp, g_K);
    cudaGetSymbolAddress((void**)&Vp, g_V);
    cudaGetSymbolAddress((void**)&Op, g_O);
    cudaGetSymbolAddress((void**)&hsT, g_hsT);
    cudaGetSymbolAddress((void**)&WqT, g_WqT);
    cudaGetSymbolAddress((void**)&WkT, g_WkT);
    cudaGetSymbolAddress((void**)&WvT, g_WvT);
    cudaGetSymbolAddress((void**)&WoT, g_WoT);
    cudaGetSymbolAddress((void**)&Qtf, g_Qtf);
    cudaGetSymbolAddress((void**)&Ktf, g_Ktf);
    cudaGetSymbolAddress((void**)&Vtf, g_Vtf);

    static bool attr_done = false;
    if (!attr_done) {
        cudaFuncSetAttribute(flash_attn_tc,
                             cudaFuncAttributeMaxDynamicSharedMemorySize,
                             ATT_SMEM_U32 * 4);
        cudaFuncSetAttribute(gemm_qkv,
                             cudaFuncAttributeMaxDynamicSharedMemorySize,
                             GEMM_SMEM_BYTES);
        cudaFuncSetAttribute(gemm_o,
                             cudaFuncAttributeMaxDynamicSharedMemorySize,
                             GEMM_SMEM_BYTES);
        attr_done = true;
    }

    // fp32 -> tf32 + pair-interleave for inputs
    {
        long long nthreads = CONV_TOTAL / 8;
        int nblk = (int)((nthreads + 255) / 256);
        conv_all<<<nblk, 256>>>(hs, Wq, Wk, Wv, Wo, hsT, WqT, WkT, WvT, WoT);
    }

    // fused QKV projection
    gemm_qkv<<<dim3(24, 16), 128, GEMM_SMEM_BYTES>>>(hsT, WqT, WkT, WvT, Qp, Kp, Vp);

    // RoPE + convert Q,K ; transpose + convert V
    rope_conv<<<(RC_TOTAL + 255) / 256, 256>>>(Qp, Kp, Qtf, Ktf);
    v_trans<<<dim3(SQ / 32, NKV), 256>>>(Vp, Vtf);

    // attention
    flash_attn_tc<<<dim3(SQ / 128, NH), 256, ATT_SMEM_U32 * 4>>>(Qtf, Ktf, Vtf, Op);

    // output projection
    gemm_o<<<dim3(16, 16), 128, GEMM_SMEM_BYTES>>>((const uint32_t*)Op, WoT, out);
}